// round 14
// baseline (speedup 1.0000x reference)
#include <cuda_runtime.h>
#include <cuda_bf16.h>
#include <math.h>
#include <stdint.h>

#define BB 16
#define NN 8192
#define CC 128
#define KK 128
#define LL 4
#define JP 256
#define KA 384            // G2 K: [2fc(128), -2fs(128), conv_w(128)] = 12*32, no padding
#define NSPLIT 8
#define KSP (NN / NSPLIT) // 1024

// ---------------- scratch (device globals) ----------------------------------
__device__ float g_wm[BB * NN];                                 // weights*size*mask
__device__ float g_mask[BB * NN];                               // mask
__device__ float g_f0[BB * CC];                                 // f_0/size (fp32, rank-1 term)
__device__ __nv_bfloat16 g_h16h[2][(size_t)BB * CC * NN];       // h split hi/lo ping-pong
__device__ __nv_bfloat16 g_h16l[2][(size_t)BB * CC * NN];
__device__ __nv_bfloat16 g_wb16h[(size_t)BB * 256 * NN];        // bases*wsz split [b][j][x]
__device__ __nv_bfloat16 g_wb16l[(size_t)BB * 256 * NN];
__device__ __nv_bfloat16 g_b16h[(size_t)BB * 256 * NN];         // bases split [b][j][x]
__device__ __nv_bfloat16 g_b16l[(size_t)BB * 256 * NN];
__device__ float g_part[(size_t)NSPLIT * BB * CC * JP];         // G1 split partials
__device__ float g_x0p[64][BB * CC];                            // x0 partials
__device__ __nv_bfloat16 g_Ah[(size_t)BB * CC * KA];            // G2 A split [b][o][j]
__device__ __nv_bfloat16 g_Al[(size_t)BB * CC * KA];
__device__ __nv_bfloat16 g_fc1h[CC * CC];                       // fc1^T split [f][c]
__device__ __nv_bfloat16 g_fc1l[CC * CC];
__device__ float g_wct[(size_t)LL * KK * CC * CC];
__device__ float g_wst[(size_t)LL * KK * CC * CC];

__device__ __forceinline__ float gelu_f(float v) {
    return 0.5f * v * (1.0f + erff(v * 0.70710678118654752f));
}
__device__ __forceinline__ void split_bf16(float v, __nv_bfloat16* hi, __nv_bfloat16* lo) {
    __nv_bfloat16 h = __float2bfloat16(v);
    *hi = h;
    *lo = __float2bfloat16(v - __bfloat162float(h));
}
// fast packed split: hi = rn(v), lo = rn(v - hi), 2 lanes at once
__device__ __forceinline__ uint32_t pack_split2(float v0, float v1, uint32_t* lo_out) {
    uint32_t ph;
    asm("cvt.rn.bf16x2.f32 %0, %1, %2;" : "=r"(ph) : "f"(v1), "f"(v0));
    const float h0 = __uint_as_float(ph << 16);
    const float h1 = __uint_as_float(ph & 0xFFFF0000u);
    uint32_t pl;
    asm("cvt.rn.bf16x2.f32 %0, %1, %2;" : "=r"(pl) : "f"(v1 - h1), "f"(v0 - h0));
    *lo_out = pl;
    return ph;
}
__device__ __forceinline__ uint32_t smem_to_u32(const void* p) {
    uint32_t a;
    asm("{ .reg .u64 t; cvta.to.shared.u64 t, %1; cvt.u32.u64 %0, t; }" : "=r"(a) : "l"(p));
    return a;
}
__device__ __forceinline__ float2 rec2(uint32_t h, uint32_t l) {
    __nv_bfloat162 hh = *(__nv_bfloat162*)&h;
    __nv_bfloat162 ll = *(__nv_bfloat162*)&l;
    return make_float2(__bfloat162float(hh.x) + __bfloat162float(ll.x),
                       __bfloat162float(hh.y) + __bfloat162float(ll.y));
}

// ---------------- FMA-pipe sincos (no MUFU): Cody-Waite + minimax ------------
__device__ __forceinline__ void fast_sincos(float t, float* sout, float* cout) {
    const float fn = rintf(t * 0.636619772f);       // 2/pi
    const int n = (int)fn;
    float r = fmaf(fn, -1.57079637e0f, t);          // pi/2 hi
    r = fmaf(fn, 4.37113883e-8f, r);                // pi/2 lo correction
    const float r2 = r * r;
    float ps = fmaf(fmaf(-1.9515296e-4f, r2, 8.3321608e-3f), r2, -1.6666654e-1f);
    ps = fmaf(ps * r2, r, r);                       // sin(r)
    float pc = fmaf(fmaf(2.44331571e-5f, r2, -1.38873163e-3f), r2, 4.16666456e-2f);
    pc = fmaf(pc, r2 * r2, fmaf(-0.5f, r2, 1.0f));  // cos(r)
    const int q = n & 3;
    float s = (q & 1) ? pc : ps;
    float c = (q & 1) ? ps : pc;
    if ((q + 1) & 2) c = -c;
    if (q & 2) s = -s;
    *sout = s;
    *cout = c;
}

// ---------------- mma.sync / ldmatrix / cp.async primitives -----------------
__device__ __forceinline__ void ldsm4(uint32_t (&d)[4], uint32_t a) {
    asm volatile("ldmatrix.sync.aligned.m8n8.x4.shared.b16 {%0,%1,%2,%3}, [%4];"
        : "=r"(d[0]), "=r"(d[1]), "=r"(d[2]), "=r"(d[3]) : "r"(a));
}
__device__ __forceinline__ void ldsm4t(uint32_t (&d)[4], uint32_t a) {
    asm volatile("ldmatrix.sync.aligned.m8n8.x4.trans.shared.b16 {%0,%1,%2,%3}, [%4];"
        : "=r"(d[0]), "=r"(d[1]), "=r"(d[2]), "=r"(d[3]) : "r"(a));
}
__device__ __forceinline__ void mma16816(float (&c)[4], const uint32_t (&a)[4], const uint32_t (&b)[2]) {
    asm volatile("mma.sync.aligned.m16n8k16.row.col.f32.bf16.bf16.f32 "
        "{%0,%1,%2,%3},{%4,%5,%6,%7},{%8,%9},{%0,%1,%2,%3};"
        : "+f"(c[0]), "+f"(c[1]), "+f"(c[2]), "+f"(c[3])
        : "r"(a[0]), "r"(a[1]), "r"(a[2]), "r"(a[3]), "r"(b[0]), "r"(b[1]));
}
__device__ __forceinline__ void cpasync16(uint32_t s, const void* g) {
    asm volatile("cp.async.cg.shared.global [%0], [%1], 16;" :: "r"(s), "l"(g));
}
#define CP_COMMIT asm volatile("cp.async.commit_group;" ::: "memory")
#define CP_WAIT1  asm volatile("cp.async.wait_group 1;" ::: "memory")

// stage layout (bytes): Ah @0, Al @8192, Bh @16384, Bl @24576; stage = 32KB, 3 stages
#define STG 32768u
#define NSTAGE 3

__device__ __forceinline__ uint32_t swzA(int r, int c) {
    return (uint32_t)(r * 64 + ((c ^ ((r >> 1) & 3)) << 4));
}
__device__ __forceinline__ uint32_t swzB(int r, int c) {
    return (uint32_t)(r * 256 + ((c ^ (r & 7)) << 4));
}

// ---------------- stage fills (256-thread CTA) --------------------------------
__device__ __forceinline__ void fill_g1(uint32_t sb, int k0, int tid,
    const __nv_bfloat16* Ah, const __nv_bfloat16* Al,
    const __nv_bfloat16* Bh, const __nv_bfloat16* Bl)
{
    #pragma unroll
    for (int q = 0; q < 8; q++) {
        const int op = q >> 1;
        const int local = ((q & 1) << 8) + tid;
        const int r = local >> 2, c = local & 3;
        const __nv_bfloat16* base = (op == 0) ? Ah : (op == 1) ? Al : (op == 2) ? Bh : Bl;
        cpasync16(sb + (uint32_t)op * 8192u + swzA(r, c),
                  base + (size_t)r * NN + k0 + c * 8);
    }
}
__device__ __forceinline__ void fill_g2(uint32_t sb, int k0, int tid,
    const __nv_bfloat16* Ah, const __nv_bfloat16* Al,
    const __nv_bfloat16* Bbh, const __nv_bfloat16* Bbl,
    const __nv_bfloat16* Hh, const __nv_bfloat16* Hl)
{
    #pragma unroll
    for (int q = 0; q < 8; q++) {
        const int op = q >> 1;
        const int local = ((q & 1) << 8) + tid;
        if (q < 4) {
            const int r = local >> 2, c = local & 3;
            const __nv_bfloat16* base = (op == 0) ? Ah : Al;
            cpasync16(sb + (uint32_t)op * 8192u + swzA(r, c),
                      base + (size_t)r * KA + k0 + c * 8);
        } else {
            const int r = local >> 4, c = local & 15;
            const int jg = k0 + r;
            const bool ishi = (q < 6);
            const __nv_bfloat16* src = (jg < 256)
                ? (ishi ? Bbh : Bbl) + (size_t)jg * NN
                : (ishi ? Hh : Hl) + (size_t)(jg - 256) * NN;
            cpasync16(sb + (uint32_t)op * 8192u + swzB(r, c), src + c * 8);
        }
    }
}
__device__ __forceinline__ void fill_fc(uint32_t sb, int k0, int tid,
    const __nv_bfloat16* Hh, const __nv_bfloat16* Hl)
{
    #pragma unroll
    for (int q = 0; q < 8; q++) {
        const int op = q >> 1;
        const int local = ((q & 1) << 8) + tid;
        if (q < 4) {
            const int r = local >> 2, c = local & 3;
            const __nv_bfloat16* base = (op == 0) ? g_fc1h : g_fc1l;
            cpasync16(sb + (uint32_t)op * 8192u + swzA(r, c),
                      base + (size_t)r * CC + k0 + c * 8);
        } else {
            const int r = local >> 4, c = local & 15;
            const __nv_bfloat16* src = ((q < 6) ? Hh : Hl) + (size_t)(k0 + r) * NN;
            cpasync16(sb + (uint32_t)op * 8192u + swzB(r, c), src + c * 8);
        }
    }
}

// ---------------- warp compute: one k32 chunk, 8 warps 64x32 tiles ------------
// (R10 form — frozen; B hoisted per k16, A loaded per-mi)
template<bool BT>
__device__ __forceinline__ void compute_chunk(uint32_t sb, int wmi, int wni, int lane,
                                              float (&acc)[4][4][4]) {
    #pragma unroll
    for (int k16 = 0; k16 < 2; k16++) {
        uint32_t bh[4][2], bl[4][2];
        #pragma unroll
        for (int g = 0; g < 2; g++) {
            uint32_t t[4], u[4];
            if (!BT) {
                const int r = wni * 32 + g * 16 + (lane & 15);
                const int c = k16 * 2 + (lane >> 4);
                const uint32_t bd = sb + 16384u + swzA(r, c);
                ldsm4(t, bd);
                ldsm4(u, bd + 8192u);
                bh[g*2+0][0] = t[0]; bh[g*2+0][1] = t[2];
                bh[g*2+1][0] = t[1]; bh[g*2+1][1] = t[3];
                bl[g*2+0][0] = u[0]; bl[g*2+0][1] = u[2];
                bl[g*2+1][0] = u[1]; bl[g*2+1][1] = u[3];
            } else {
                const int r = k16 * 16 + (lane & 15);
                const int c = wni * 4 + g * 2 + (lane >> 4);
                const uint32_t bd = sb + 16384u + swzB(r, c);
                ldsm4t(t, bd);
                ldsm4t(u, bd + 8192u);
                bh[g*2+0][0] = t[0]; bh[g*2+0][1] = t[1];
                bh[g*2+1][0] = t[2]; bh[g*2+1][1] = t[3];
                bl[g*2+0][0] = u[0]; bl[g*2+0][1] = u[1];
                bl[g*2+1][0] = u[2]; bl[g*2+1][1] = u[3];
            }
        }
        #pragma unroll
        for (int mi = 0; mi < 4; mi++) {
            uint32_t ah[4], al[4];
            {
                const int r = wmi * 64 + mi * 16 + (lane & 15);
                const int c = k16 * 2 + (lane >> 4);
                const uint32_t ad = sb + swzA(r, c);
                ldsm4(ah, ad);
                ldsm4(al, ad + 8192u);
            }
            #pragma unroll
            for (int ni = 0; ni < 4; ni++) {
                mma16816(acc[mi][ni], ah, bh[ni]);
                mma16816(acc[mi][ni], ah, bl[ni]);
                mma16816(acc[mi][ni], al, bh[ni]);
            }
        }
    }
}

// ---------------- G1: D[i=128][j=128-tile] = sum_x h*wb ----------------------
__global__ __launch_bounds__(256, 2) void k_mma_g1(int cur) {
    extern __shared__ __align__(128) char dsm[];
    const uint32_t sb0 = smem_to_u32(dsm);
    const int tid = threadIdx.x, lane = tid & 31, wid = tid >> 5;
    const int wmi = wid >> 2, wni = wid & 3;
    const int nt = blockIdx.x, sp = blockIdx.y, b = blockIdx.z;
    const __nv_bfloat16* Ah = g_h16h[cur] + (size_t)b * CC * NN + (size_t)sp * KSP;
    const __nv_bfloat16* Al = g_h16l[cur] + (size_t)b * CC * NN + (size_t)sp * KSP;
    const __nv_bfloat16* Bh = g_wb16h + ((size_t)b * 256 + nt * 128) * NN + (size_t)sp * KSP;
    const __nv_bfloat16* Bl = g_wb16l + ((size_t)b * 256 + nt * 128) * NN + (size_t)sp * KSP;
    float acc[4][4][4] = {};
    const int niter = KSP / 32;    // 32
    fill_g1(sb0, 0, tid, Ah, Al, Bh, Bl);
    CP_COMMIT;
    fill_g1(sb0 + STG, 32, tid, Ah, Al, Bh, Bl);
    CP_COMMIT;
    int fs = 2;
    for (int it = 0; it < niter; ++it) {
        CP_WAIT1;
        __syncthreads();
        if (it + 2 < niter) {
            fill_g1(sb0 + (uint32_t)fs * STG, (it + 2) * 32, tid, Ah, Al, Bh, Bl);
        }
        CP_COMMIT;
        const int cs = (fs + 1 == NSTAGE) ? 0 : fs + 1;
        compute_chunk<false>(sb0 + (uint32_t)((it % NSTAGE)) * STG, wmi, wni, lane, acc);
        fs = cs;
    }
    float* pp = g_part + (((size_t)sp * BB + b) * CC) * JP + nt * 128;
    #pragma unroll
    for (int mi = 0; mi < 4; mi++) {
        #pragma unroll
        for (int ni = 0; ni < 4; ni++) {
            const int m = wmi * 64 + mi * 16 + (lane >> 2);
            const int n = wni * 32 + ni * 8 + (lane & 3) * 2;
            *(float2*)&pp[(size_t)m * JP + n]       = make_float2(acc[mi][ni][0], acc[mi][ni][1]);
            *(float2*)&pp[(size_t)(m + 8) * JP + n] = make_float2(acc[mi][ni][2], acc[mi][ni][3]);
        }
    }
}

// ---------------- G2: D[o=128][x=128-tile] = sum_j A*[bases;h] ---------------
// epilogue: + conv_b + f0*mask, gelu, bf16 split write, x0 partials
__global__ __launch_bounds__(256, 2) void k_mma_g2(int cur, int nxt,
                                                   const float* __restrict__ conv_b,
                                                   int l, int dogelu, int dox0) {
    extern __shared__ __align__(128) char dsm[];
    __shared__ float scb[128];
    __shared__ float s_wm[128];
    __shared__ float s_f0[128];
    __shared__ float s_mask[128];
    __shared__ float s_part[128][16];
    const uint32_t sb0 = smem_to_u32(dsm);
    const int tid = threadIdx.x, lane = tid & 31, wid = tid >> 5;
    const int wmi = wid >> 2, wni = wid & 3;
    const int xt = blockIdx.x, b = blockIdx.y;
    if (tid < 128) {
        scb[tid] = conv_b[l * CC + tid];
        s_wm[tid] = g_wm[(size_t)b * NN + (size_t)xt * 128 + tid];
        s_f0[tid] = g_f0[b * CC + tid];
        s_mask[tid] = g_mask[(size_t)b * NN + (size_t)xt * 128 + tid];
    }
    const __nv_bfloat16* Ah = g_Ah + (size_t)b * CC * KA;
    const __nv_bfloat16* Al = g_Al + (size_t)b * CC * KA;
    const __nv_bfloat16* Bbh = g_b16h + (size_t)b * 256 * NN + (size_t)xt * 128;
    const __nv_bfloat16* Bbl = g_b16l + (size_t)b * 256 * NN + (size_t)xt * 128;
    const __nv_bfloat16* Hh = g_h16h[cur] + (size_t)b * CC * NN + (size_t)xt * 128;
    const __nv_bfloat16* Hl = g_h16l[cur] + (size_t)b * CC * NN + (size_t)xt * 128;
    float acc[4][4][4] = {};
    const int niter = KA / 32;   // 12
    fill_g2(sb0, 0, tid, Ah, Al, Bbh, Bbl, Hh, Hl);
    CP_COMMIT;
    fill_g2(sb0 + STG, 32, tid, Ah, Al, Bbh, Bbl, Hh, Hl);
    CP_COMMIT;
    int fs = 2;
    for (int it = 0; it < niter; ++it) {
        CP_WAIT1;
        __syncthreads();
        if (it + 2 < niter) {
            fill_g2(sb0 + (uint32_t)fs * STG, (it + 2) * 32, tid, Ah, Al, Bbh, Bbl, Hh, Hl);
        }
        CP_COMMIT;
        const int cs = (fs + 1 == NSTAGE) ? 0 : fs + 1;
        compute_chunk<true>(sb0 + (uint32_t)((it % NSTAGE)) * STG, wmi, wni, lane, acc);
        fs = cs;
    }
    __syncthreads();
    __nv_bfloat16* hh = g_h16h[nxt] + (size_t)b * CC * NN + (size_t)xt * 128;
    __nv_bfloat16* hl = g_h16l[nxt] + (size_t)b * CC * NN + (size_t)xt * 128;
    float sx[8] = {};
    #pragma unroll
    for (int mi = 0; mi < 4; mi++) {
        #pragma unroll
        for (int ni = 0; ni < 4; ni++) {
            const int n = wni * 32 + ni * 8 + (lane & 3) * 2;
            #pragma unroll
            for (int half = 0; half < 2; half++) {
                const int o = wmi * 64 + mi * 16 + (lane >> 2) + half * 8;
                const float f0o = s_f0[o];
                float v0 = acc[mi][ni][half * 2 + 0] + scb[o] + f0o * s_mask[n];
                float v1 = acc[mi][ni][half * 2 + 1] + scb[o] + f0o * s_mask[n + 1];
                if (dogelu) { v0 = gelu_f(v0); v1 = gelu_f(v1); }
                uint32_t pl, ph = pack_split2(v0, v1, &pl);
                *(uint32_t*)&hh[(size_t)o * NN + n] = ph;
                *(uint32_t*)&hl[(size_t)o * NN + n] = pl;
                if (dox0) {
                    sx[mi * 2 + half] = fmaf(v0, s_wm[n], sx[mi * 2 + half]);
                    sx[mi * 2 + half] = fmaf(v1, s_wm[n + 1], sx[mi * 2 + half]);
                }
            }
        }
    }
    if (dox0) {
        const int slot = wni * 4 + (lane & 3);
        #pragma unroll
        for (int mi = 0; mi < 4; mi++)
            #pragma unroll
            for (int half = 0; half < 2; half++) {
                const int o = wmi * 64 + mi * 16 + (lane >> 2) + half * 8;
                s_part[o][slot] = sx[mi * 2 + half];
            }
        __syncthreads();
        if (tid < 128) {
            float s = 0.f;
            #pragma unroll
            for (int q = 0; q < 16; q++) s += s_part[tid][q];
            g_x0p[xt][b * CC + tid] = s;
        }
    }
}

// ---------------- final MLP as MMA: y[x] = fc2 . gelu(fc1T @ h + b1) + b2 ----
__global__ __launch_bounds__(256, 2) void k_final_mma(const float* __restrict__ fc1_b,
                                                      const float* __restrict__ fc2_w,
                                                      const float* __restrict__ fc2_b,
                                                      float* __restrict__ out) {
    extern __shared__ __align__(128) char dsm[];
    __shared__ float s_fb[128];
    __shared__ float s_w2[128];
    __shared__ float s_red[128][17];
    const uint32_t sb0 = smem_to_u32(dsm);
    const int tid = threadIdx.x, lane = tid & 31, wid = tid >> 5;
    const int wmi = wid >> 2, wni = wid & 3;
    const int xt = blockIdx.x, b = blockIdx.y;
    if (tid < 128) { s_fb[tid] = fc1_b[tid]; s_w2[tid] = fc2_w[tid]; }
    const __nv_bfloat16* Hh = g_h16h[0] + (size_t)b * CC * NN + (size_t)xt * 128;
    const __nv_bfloat16* Hl = g_h16l[0] + (size_t)b * CC * NN + (size_t)xt * 128;
    float acc[4][4][4] = {};
    const int niter = CC / 32;   // 4
    fill_fc(sb0, 0, tid, Hh, Hl);
    CP_COMMIT;
    fill_fc(sb0 + STG, 32, tid, Hh, Hl);
    CP_COMMIT;
    int fs = 2;
    for (int it = 0; it < niter; ++it) {
        CP_WAIT1;
        __syncthreads();
        if (it + 2 < niter) {
            fill_fc(sb0 + (uint32_t)fs * STG, (it + 2) * 32, tid, Hh, Hl);
        }
        CP_COMMIT;
        const int cs = (fs + 1 == NSTAGE) ? 0 : fs + 1;
        compute_chunk<true>(sb0 + (uint32_t)((it % NSTAGE)) * STG, wmi, wni, lane, acc);
        fs = cs;
    }
    __syncthreads();
    float xs[8] = {};
    #pragma unroll
    for (int mi = 0; mi < 4; mi++) {
        #pragma unroll
        for (int ni = 0; ni < 4; ni++) {
            #pragma unroll
            for (int half = 0; half < 2; half++) {
                const int f = wmi * 64 + mi * 16 + (lane >> 2) + half * 8;
                const float w2 = s_w2[f], b1 = s_fb[f];
                xs[ni * 2 + 0] = fmaf(w2, gelu_f(acc[mi][ni][half * 2 + 0] + b1), xs[ni * 2 + 0]);
                xs[ni * 2 + 1] = fmaf(w2, gelu_f(acc[mi][ni][half * 2 + 1] + b1), xs[ni * 2 + 1]);
            }
        }
    }
    const int slot = wmi * 8 + (lane >> 2);
    #pragma unroll
    for (int ni = 0; ni < 4; ni++) {
        #pragma unroll
        for (int p = 0; p < 2; p++) {
            const int x = wni * 32 + ni * 8 + (lane & 3) * 2 + p;
            s_red[x][slot] = xs[ni * 2 + p];
        }
    }
    __syncthreads();
    if (tid < 128) {
        float s = fc2_b[0];
        #pragma unroll
        for (int q = 0; q < 16; q++) s += s_red[tid][q];
        out[(size_t)b * NN + (size_t)xt * 128 + tid] = s;
    }
}

// ---------------- weight transpose (once) ------------------------------------
__global__ void k_wtrans(const float* __restrict__ wc, const float* __restrict__ ws) {
    __shared__ float sm[32][33];
    const int tile = blockIdx.x;
    const int o0 = (tile >> 2) * 32, k0 = (tile & 3) * 32;
    const int i = blockIdx.y, l = blockIdx.z;
    const float scale = 1.0f / 8192.0f;
    for (int w = 0; w < 2; w++) {
        const float* src = w ? ws : wc;
        float* dst = w ? g_wst : g_wct;
        #pragma unroll
        for (int s = 0; s < 4; s++) {
            int oo = threadIdx.y + 8 * s, kk = threadIdx.x;
            sm[oo][kk] = src[(((size_t)l * CC + i) * CC + (o0 + oo)) * KK + (k0 + kk)] * scale;
        }
        __syncthreads();
        #pragma unroll
        for (int s = 0; s < 4; s++) {
            int kk = threadIdx.y + 8 * s, oo = threadIdx.x;
            dst[(((size_t)l * KK + (k0 + kk)) * CC + i) * CC + (o0 + oo)] = sm[oo][kk];
        }
        __syncthreads();
    }
}

// ---------------- fc1^T split prep (once, tiny) -------------------------------
__global__ void k_prepfc(const float* __restrict__ fc1_w) {
    const int f = blockIdx.x, c = threadIdx.x;
    __nv_bfloat16 hi, lo;
    split_bf16(fc1_w[c * CC + f], &hi, &lo);
    g_fc1h[f * CC + c] = hi;
    g_fc1l[f * CC + c] = lo;
}

// ---------------- precompute (4-way k-split): bases16, wb16, wm, mask, h0 -----
// grid (BB*NN/512, 4); blockIdx.y = y handles modes [32y,32y+32) and h0
// channels [32y,32y+32); y==0 additionally writes wm/mask.
__global__ __launch_bounds__(256) void k_pre(const float* __restrict__ xin,
                                             const float* __restrict__ modes,
                                             const float* __restrict__ fc0_w,
                                             const float* __restrict__ fc0_b) {
    __shared__ float sm_modes[64];
    __shared__ float sm_w[384];
    __shared__ float sm_b[128];
    const int t = threadIdx.x;
    const int y = blockIdx.y;
    const int kbase = y * 32;
    if (t < 64) sm_modes[t] = modes[kbase * 2 + t];
    if (t < 128) {
        sm_w[t] = fc0_w[t];
        sm_w[128 + t] = fc0_w[128 + t];
        sm_w[256 + t] = fc0_w[256 + t];
        sm_b[t] = fc0_b[t];
    }
    __syncthreads();

    const int gid = (blockIdx.x * 256 + t) * 2;       // even x pair over B*N
    const int b = gid / NN, xx = gid - b * NN;
    const float* xr = xin + (size_t)gid * 7;
    const float p0i0 = xr[0], p0i1 = xr[1], p0i2 = xr[2];
    const float p0d0 = xr[3], p0d1 = xr[4], p0w = xr[5], p0m = xr[6];
    const float p1i0 = xr[7], p1i1 = xr[8], p1i2 = xr[9];
    const float p1d0 = xr[10], p1d1 = xr[11], p1w = xr[12], p1m = xr[13];

    const float wsz0 = p0w * (float)NN, wsz1 = p1w * (float)NN;
    if (y == 0) {
        *(float2*)&g_wm[gid] = make_float2(wsz0 * p0m, wsz1 * p1m);
        *(float2*)&g_mask[gid] = make_float2(p0m, p1m);
    }

    uint32_t* bh = (uint32_t*)(g_b16h + (size_t)b * 256 * NN + xx);
    uint32_t* bl = (uint32_t*)(g_b16l + (size_t)b * 256 * NN + xx);
    uint32_t* wbh = (uint32_t*)(g_wb16h + (size_t)b * 256 * NN + xx);
    uint32_t* wbl = (uint32_t*)(g_wb16l + (size_t)b * 256 * NN + xx);
    #pragma unroll 2
    for (int kk = 0; kk < 32; kk++) {
        const int k = kbase + kk;
        const float m0 = sm_modes[2 * kk], m1 = sm_modes[2 * kk + 1];
        float s0, c0, s1, c1;
        fast_sincos(fmaf(p0d0, m0, p0d1 * m1), &s0, &c0);
        fast_sincos(fmaf(p1d0, m0, p1d1 * m1), &s1, &c1);
        const float cm0 = c0 * p0m, sm0 = s0 * p0m;
        const float cm1 = c1 * p1m, sm1 = s1 * p1m;
        uint32_t lo, hi;
        hi = pack_split2(cm0, cm1, &lo);
        bh[(size_t)k * (NN / 2)] = hi; bl[(size_t)k * (NN / 2)] = lo;
        hi = pack_split2(sm0, sm1, &lo);
        bh[(size_t)(128 + k) * (NN / 2)] = hi; bl[(size_t)(128 + k) * (NN / 2)] = lo;
        hi = pack_split2(cm0 * wsz0, cm1 * wsz1, &lo);
        wbh[(size_t)k * (NN / 2)] = hi; wbl[(size_t)k * (NN / 2)] = lo;
        hi = pack_split2(sm0 * wsz0, sm1 * wsz1, &lo);
        wbh[(size_t)(128 + k) * (NN / 2)] = hi; wbl[(size_t)(128 + k) * (NN / 2)] = lo;
    }
    uint32_t* h16h = (uint32_t*)(g_h16h[0] + (size_t)b * CC * NN + xx);
    uint32_t* h16l = (uint32_t*)(g_h16l[0] + (size_t)b * CC * NN + xx);
    #pragma unroll 4
    for (int cc = 0; cc < 32; cc++) {
        const int c = kbase + cc;
        float v0 = sm_b[c], v1 = sm_b[c];
        v0 = fmaf(p0i0, sm_w[c], v0);
        v0 = fmaf(p0i1, sm_w[128 + c], v0);
        v0 = fmaf(p0i2, sm_w[256 + c], v0);
        v1 = fmaf(p1i0, sm_w[c], v1);
        v1 = fmaf(p1i1, sm_w[128 + c], v1);
        v1 = fmaf(p1i2, sm_w[256 + c], v1);
        uint32_t lo, hi = pack_split2(v0, v1, &lo);
        h16h[(size_t)c * (NN / 2)] = hi;
        h16l[(size_t)c * (NN / 2)] = lo;
    }
}

// ---------------- x_0 partials for layer 0 (reads h0 splits) ------------------
__global__ __launch_bounds__(256) void k_x0() {
    const int b = blockIdx.x;
    const int i = blockIdx.y * 8 + (threadIdx.x >> 5);
    const int z = blockIdx.z;
    const int lane = threadIdx.x & 31;
    const int q = NN / 32;
    const uint4* hp = (const uint4*)(g_h16h[0] + ((size_t)b * CC + i) * NN) + (size_t)z * q;
    const uint4* lp = (const uint4*)(g_h16l[0] + ((size_t)b * CC + i) * NN) + (size_t)z * q;
    const float4* wp = (const float4*)(g_wm + (size_t)b * NN) + (size_t)z * q * 2;
    float s = 0.f;
    for (int t = lane; t < q; t += 32) {
        uint4 hv = hp[t], lv = lp[t];
        float4 w0 = wp[2 * t], w1 = wp[2 * t + 1];
        float2 v0 = rec2(hv.x, lv.x), v1 = rec2(hv.y, lv.y);
        float2 v2 = rec2(hv.z, lv.z), v3 = rec2(hv.w, lv.w);
        s = fmaf(v0.x, w0.x, s); s = fmaf(v0.y, w0.y, s);
        s = fmaf(v1.x, w0.z, s); s = fmaf(v1.y, w0.w, s);
        s = fmaf(v2.x, w1.x, s); s = fmaf(v2.y, w1.y, s);
        s = fmaf(v3.x, w1.z, s); s = fmaf(v3.y, w1.w, s);
    }
    #pragma unroll
    for (int off = 16; off; off >>= 1) s += __shfl_xor_sync(0xffffffffu, s, off);
    if (!lane) g_x0p[z][b * CC + i] = s;
}

// ---------------- k_mid: fused fmix (bx<128) + f0/conv (bx>=128) --------------
__global__ __launch_bounds__(128) void k_mid(const float* __restrict__ w0,
                                             const float* __restrict__ conv_w,
                                             int l, int npart) {
    const int t = threadIdx.x;
    if (blockIdx.x < 128) {
        const int k = blockIdx.x;
        const int bh = blockIdx.y * 8;
        __shared__ float xc_s[128][8];
        __shared__ float xs_s[128][8];
        #pragma unroll
        for (int b = 0; b < 8; b++) {
            float sc = 0.f, ss = 0.f;
            #pragma unroll
            for (int s = 0; s < NSPLIT; s++) {
                const float* pp = g_part + (((size_t)s * BB + bh + b) * CC + t) * JP;
                sc += pp[k];
                ss += pp[128 + k];
            }
            xc_s[t][b] = sc;
            xs_s[t][b] = -ss;
        }
        __syncthreads();
        float fc[8] = {}, fs[8] = {};
        const float* wcp = g_wct + ((size_t)(l * KK + k)) * CC * CC + t;
        const float* wsp = g_wst + ((size_t)(l * KK + k)) * CC * CC + t;
        #pragma unroll 4
        for (int i = 0; i < 128; i++) {
            const float wcv = wcp[(size_t)i * CC], wsv = wsp[(size_t)i * CC];
            #pragma unroll
            for (int b = 0; b < 8; b++) {
                const float cv = xc_s[i][b], sv = xs_s[i][b];
                fc[b] = fmaf(cv, wcv, fc[b]); fc[b] = fmaf(-sv, wsv, fc[b]);
                fs[b] = fmaf(sv, wcv, fs[b]); fs[b] = fmaf(cv, wsv, fs[b]);
            }
        }
        #pragma unroll
        for (int b = 0; b < 8; b++) {
            const size_t base = ((size_t)(bh + b) * CC + t) * KA;
            __nv_bfloat16 hi, lo;
            split_bf16(2.f * fc[b], &hi, &lo);
            g_Ah[base + k] = hi; g_Al[base + k] = lo;
            split_bf16(-2.f * fs[b], &hi, &lo);
            g_Ah[base + 128 + k] = hi; g_Al[base + 128 + k] = lo;
        }
    } else {
        const int b = (blockIdx.x - 128) + blockIdx.y * 8;
        __shared__ float x0s[128];
        float s = 0.f;
        for (int p = 0; p < npart; p++) s += g_x0p[p][b * CC + t];
        x0s[t] = s;
        __syncthreads();
        float f0 = 0.f;
        const float* w0p = w0 + (size_t)l * CC * CC;
        #pragma unroll 8
        for (int i = 0; i < 128; i++) f0 = fmaf(x0s[i], w0p[(size_t)i * CC + t], f0);
        g_f0[b * CC + t] = f0 * (1.0f / 8192.0f);     // fp32 rank-1 term (epilogue)
        const size_t base = ((size_t)b * CC + t) * KA;
        __nv_bfloat16 hi, lo;
        const float* cw = conv_w + ((size_t)(l * CC) + t) * CC;
        #pragma unroll 8
        for (int i = 0; i < 128; i++) {
            split_bf16(cw[i], &hi, &lo);
            g_Ah[base + 256 + i] = hi; g_Al[base + 256 + i] = lo;
        }
    }
}

// ---------------- launch -------------------------------------------------------
extern "C" void kernel_launch(void* const* d_in, const int* in_sizes, int n_in,
                              void* d_out, int out_size) {
    const float* x      = (const float*)d_in[0];
    const float* modes  = (const float*)d_in[1];
    const float* fc0_w  = (const float*)d_in[2];
    const float* fc0_b  = (const float*)d_in[3];
    const float* wc     = (const float*)d_in[4];
    const float* ws     = (const float*)d_in[5];
    const float* w0     = (const float*)d_in[6];
    const float* conv_w = (const float*)d_in[7];
    const float* conv_b = (const float*)d_in[8];
    const float* fc1_w  = (const float*)d_in[9];
    const float* fc1_b  = (const float*)d_in[10];
    const float* fc2_w  = (const float*)d_in[11];
    const float* fc2_b  = (const float*)d_in[12];
    float* out = (float*)d_out;

    const int smem = NSTAGE * (int)STG;   // 96KB
    cudaFuncSetAttribute(k_mma_g1, cudaFuncAttributeMaxDynamicSharedMemorySize, smem);
    cudaFuncSetAttribute(k_mma_g2, cudaFuncAttributeMaxDynamicSharedMemorySize, smem);
    cudaFuncSetAttribute(k_final_mma, cudaFuncAttributeMaxDynamicSharedMemorySize, smem);

    k_wtrans<<<dim3(16, 128, 4), dim3(32, 8)>>>(wc, ws);
    k_prepfc<<<CC, CC>>>(fc1_w);
    k_pre<<<dim3((BB * NN) / 512, 4), 256>>>(x, modes, fc0_w, fc0_b);
    k_x0<<<dim3(BB, 16, 4), 256>>>();
    for (int l = 0; l < LL; l++) {
        const int cur = l & 1, nxt = cur ^ 1;
        k_mma_g1<<<dim3(2, NSPLIT, BB), 256, smem>>>(cur);
        k_mid<<<dim3(136, 2), 128>>>(w0, conv_w, l, (l == 0) ? 4 : 64);
        k_mma_g2<<<dim3(NN / 128, BB), 256, smem>>>(cur, nxt, conv_b, l,
                                                    (l < LL - 1) ? 1 : 0,
                                                    (l < LL - 1) ? 1 : 0);
    }
    k_final_mma<<<dim3(NN / 128, BB), 256, smem>>>(fc1_b, fc2_w, fc2_b, out);
}

// round 15
// speedup vs baseline: 1.0001x; 1.0001x over previous
#include <cuda_runtime.h>
#include <cuda_bf16.h>
#include <math.h>
#include <stdint.h>

#define BB 16
#define NN 8192
#define CC 128
#define KK 128
#define LL 4
#define JP 256
#define KA 384            // G2 K: [2fc(128), -2fs(128), conv_w(128)] = 12*32, no padding
#define NSPLIT 8
#define KSP (NN / NSPLIT) // 1024

// ---------------- scratch (device globals) ----------------------------------
__device__ float g_wm[BB * NN];                                 // weights*size*mask
__device__ float g_mask[BB * NN];                               // mask
__device__ float g_f0[BB * CC];                                 // f_0/size (fp32, rank-1 term)
__device__ __nv_bfloat16 g_h16h[2][(size_t)BB * CC * NN];       // h split hi/lo ping-pong
__device__ __nv_bfloat16 g_h16l[2][(size_t)BB * CC * NN];
__device__ __nv_bfloat16 g_wb16h[(size_t)BB * 256 * NN];        // bases*wsz split [b][j][x]
__device__ __nv_bfloat16 g_wb16l[(size_t)BB * 256 * NN];
__device__ __nv_bfloat16 g_b16h[(size_t)BB * 256 * NN];         // bases split [b][j][x]
__device__ __nv_bfloat16 g_b16l[(size_t)BB * 256 * NN];
__device__ float g_part[(size_t)NSPLIT * BB * CC * JP];         // G1 split partials
__device__ float g_x0p[64][BB * CC];                            // x0 partials
__device__ __nv_bfloat16 g_Ah[(size_t)BB * CC * KA];            // G2 A split [b][o][j]
__device__ __nv_bfloat16 g_Al[(size_t)BB * CC * KA];
__device__ __nv_bfloat16 g_fc1h[CC * CC];                       // fc1^T split [f][c]
__device__ __nv_bfloat16 g_fc1l[CC * CC];
__device__ float g_wct[(size_t)LL * KK * CC * CC];
__device__ float g_wst[(size_t)LL * KK * CC * CC];

__device__ __forceinline__ float gelu_f(float v) {
    return 0.5f * v * (1.0f + erff(v * 0.70710678118654752f));
}
__device__ __forceinline__ void split_bf16(float v, __nv_bfloat16* hi, __nv_bfloat16* lo) {
    __nv_bfloat16 h = __float2bfloat16(v);
    *hi = h;
    *lo = __float2bfloat16(v - __bfloat162float(h));
}
// fast packed split: hi = rn(v), lo = rn(v - hi), 2 lanes at once
__device__ __forceinline__ uint32_t pack_split2(float v0, float v1, uint32_t* lo_out) {
    uint32_t ph;
    asm("cvt.rn.bf16x2.f32 %0, %1, %2;" : "=r"(ph) : "f"(v1), "f"(v0));
    const float h0 = __uint_as_float(ph << 16);
    const float h1 = __uint_as_float(ph & 0xFFFF0000u);
    uint32_t pl;
    asm("cvt.rn.bf16x2.f32 %0, %1, %2;" : "=r"(pl) : "f"(v1 - h1), "f"(v0 - h0));
    *lo_out = pl;
    return ph;
}
__device__ __forceinline__ uint32_t smem_to_u32(const void* p) {
    uint32_t a;
    asm("{ .reg .u64 t; cvta.to.shared.u64 t, %1; cvt.u32.u64 %0, t; }" : "=r"(a) : "l"(p));
    return a;
}

// ---------------- FMA-pipe sincos (no MUFU): Cody-Waite + minimax ------------
__device__ __forceinline__ void fast_sincos(float t, float* sout, float* cout) {
    const float fn = rintf(t * 0.636619772f);       // 2/pi
    const int n = (int)fn;
    float r = fmaf(fn, -1.57079637e0f, t);          // pi/2 hi
    r = fmaf(fn, 4.37113883e-8f, r);                // pi/2 lo correction
    const float r2 = r * r;
    float ps = fmaf(fmaf(-1.9515296e-4f, r2, 8.3321608e-3f), r2, -1.6666654e-1f);
    ps = fmaf(ps * r2, r, r);                       // sin(r)
    float pc = fmaf(fmaf(2.44331571e-5f, r2, -1.38873163e-3f), r2, 4.16666456e-2f);
    pc = fmaf(pc, r2 * r2, fmaf(-0.5f, r2, 1.0f));  // cos(r)
    const int q = n & 3;
    float s = (q & 1) ? pc : ps;
    float c = (q & 1) ? ps : pc;
    if ((q + 1) & 2) c = -c;
    if (q & 2) s = -s;
    *sout = s;
    *cout = c;
}

// ---------------- mma.sync / ldmatrix / cp.async primitives -----------------
__device__ __forceinline__ void ldsm4(uint32_t (&d)[4], uint32_t a) {
    asm volatile("ldmatrix.sync.aligned.m8n8.x4.shared.b16 {%0,%1,%2,%3}, [%4];"
        : "=r"(d[0]), "=r"(d[1]), "=r"(d[2]), "=r"(d[3]) : "r"(a));
}
__device__ __forceinline__ void ldsm4t(uint32_t (&d)[4], uint32_t a) {
    asm volatile("ldmatrix.sync.aligned.m8n8.x4.trans.shared.b16 {%0,%1,%2,%3}, [%4];"
        : "=r"(d[0]), "=r"(d[1]), "=r"(d[2]), "=r"(d[3]) : "r"(a));
}
__device__ __forceinline__ void mma16816(float (&c)[4], const uint32_t (&a)[4], const uint32_t (&b)[2]) {
    asm volatile("mma.sync.aligned.m16n8k16.row.col.f32.bf16.bf16.f32 "
        "{%0,%1,%2,%3},{%4,%5,%6,%7},{%8,%9},{%0,%1,%2,%3};"
        : "+f"(c[0]), "+f"(c[1]), "+f"(c[2]), "+f"(c[3])
        : "r"(a[0]), "r"(a[1]), "r"(a[2]), "r"(a[3]), "r"(b[0]), "r"(b[1]));
}
__device__ __forceinline__ void cpasync16(uint32_t s, const void* g) {
    asm volatile("cp.async.cg.shared.global [%0], [%1], 16;" :: "r"(s), "l"(g));
}
#define CP_COMMIT asm volatile("cp.async.commit_group;" ::: "memory")
#define CP_WAIT1  asm volatile("cp.async.wait_group 1;" ::: "memory")

// stage layout (bytes): Ah @0, Al @8192, Bh @16384, Bl @24576; stage = 32KB, 3 stages
#define STG 32768u
#define NSTAGE 3

__device__ __forceinline__ uint32_t swzA(int r, int c) {
    return (uint32_t)(r * 64 + ((c ^ ((r >> 1) & 3)) << 4));
}
__device__ __forceinline__ uint32_t swzB(int r, int c) {
    return (uint32_t)(r * 256 + ((c ^ (r & 7)) << 4));
}

// ---------------- stage fills (256-thread CTA) --------------------------------
__device__ __forceinline__ void fill_g1(uint32_t sb, int k0, int tid,
    const __nv_bfloat16* Ah, const __nv_bfloat16* Al,
    const __nv_bfloat16* Bh, const __nv_bfloat16* Bl)
{
    #pragma unroll
    for (int q = 0; q < 8; q++) {
        const int op = q >> 1;
        const int local = ((q & 1) << 8) + tid;
        const int r = local >> 2, c = local & 3;
        const __nv_bfloat16* base = (op == 0) ? Ah : (op == 1) ? Al : (op == 2) ? Bh : Bl;
        cpasync16(sb + (uint32_t)op * 8192u + swzA(r, c),
                  base + (size_t)r * NN + k0 + c * 8);
    }
}
__device__ __forceinline__ void fill_g2(uint32_t sb, int k0, int tid,
    const __nv_bfloat16* Ah, const __nv_bfloat16* Al,
    const __nv_bfloat16* Bbh, const __nv_bfloat16* Bbl,
    const __nv_bfloat16* Hh, const __nv_bfloat16* Hl)
{
    #pragma unroll
    for (int q = 0; q < 8; q++) {
        const int op = q >> 1;
        const int local = ((q & 1) << 8) + tid;
        if (q < 4) {
            const int r = local >> 2, c = local & 3;
            const __nv_bfloat16* base = (op == 0) ? Ah : Al;
            cpasync16(sb + (uint32_t)op * 8192u + swzA(r, c),
                      base + (size_t)r * KA + k0 + c * 8);
        } else {
            const int r = local >> 4, c = local & 15;
            const int jg = k0 + r;
            const bool ishi = (q < 6);
            const __nv_bfloat16* src = (jg < 256)
                ? (ishi ? Bbh : Bbl) + (size_t)jg * NN
                : (ishi ? Hh : Hl) + (size_t)(jg - 256) * NN;
            cpasync16(sb + (uint32_t)op * 8192u + swzB(r, c), src + c * 8);
        }
    }
}
__device__ __forceinline__ void fill_fc(uint32_t sb, int k0, int tid,
    const __nv_bfloat16* Hh, const __nv_bfloat16* Hl)
{
    #pragma unroll
    for (int q = 0; q < 8; q++) {
        const int op = q >> 1;
        const int local = ((q & 1) << 8) + tid;
        if (q < 4) {
            const int r = local >> 2, c = local & 3;
            const __nv_bfloat16* base = (op == 0) ? g_fc1h : g_fc1l;
            cpasync16(sb + (uint32_t)op * 8192u + swzA(r, c),
                      base + (size_t)r * CC + k0 + c * 8);
        } else {
            const int r = local >> 4, c = local & 15;
            const __nv_bfloat16* src = ((q < 6) ? Hh : Hl) + (size_t)(k0 + r) * NN;
            cpasync16(sb + (uint32_t)op * 8192u + swzB(r, c), src + c * 8);
        }
    }
}

// ---------------- warp compute: one k32 chunk, 8 warps 64x32 tiles ------------
// (R10 form — frozen; B hoisted per k16, A loaded per-mi)
template<bool BT>
__device__ __forceinline__ void compute_chunk(uint32_t sb, int wmi, int wni, int lane,
                                              float (&acc)[4][4][4]) {
    #pragma unroll
    for (int k16 = 0; k16 < 2; k16++) {
        uint32_t bh[4][2], bl[4][2];
        #pragma unroll
        for (int g = 0; g < 2; g++) {
            uint32_t t[4], u[4];
            if (!BT) {
                const int r = wni * 32 + g * 16 + (lane & 15);
                const int c = k16 * 2 + (lane >> 4);
                const uint32_t bd = sb + 16384u + swzA(r, c);
                ldsm4(t, bd);
                ldsm4(u, bd + 8192u);
                bh[g*2+0][0] = t[0]; bh[g*2+0][1] = t[2];
                bh[g*2+1][0] = t[1]; bh[g*2+1][1] = t[3];
                bl[g*2+0][0] = u[0]; bl[g*2+0][1] = u[2];
                bl[g*2+1][0] = u[1]; bl[g*2+1][1] = u[3];
            } else {
                const int r = k16 * 16 + (lane & 15);
                const int c = wni * 4 + g * 2 + (lane >> 4);
                const uint32_t bd = sb + 16384u + swzB(r, c);
                ldsm4t(t, bd);
                ldsm4t(u, bd + 8192u);
                bh[g*2+0][0] = t[0]; bh[g*2+0][1] = t[1];
                bh[g*2+1][0] = t[2]; bh[g*2+1][1] = t[3];
                bl[g*2+0][0] = u[0]; bl[g*2+0][1] = u[1];
                bl[g*2+1][0] = u[2]; bl[g*2+1][1] = u[3];
            }
        }
        #pragma unroll
        for (int mi = 0; mi < 4; mi++) {
            uint32_t ah[4], al[4];
            {
                const int r = wmi * 64 + mi * 16 + (lane & 15);
                const int c = k16 * 2 + (lane >> 4);
                const uint32_t ad = sb + swzA(r, c);
                ldsm4(ah, ad);
                ldsm4(al, ad + 8192u);
            }
            #pragma unroll
            for (int ni = 0; ni < 4; ni++) {
                mma16816(acc[mi][ni], ah, bh[ni]);
                mma16816(acc[mi][ni], ah, bl[ni]);
                mma16816(acc[mi][ni], al, bh[ni]);
            }
        }
    }
}

// ---------------- G1: D[i=128][j=128-tile] = sum_x h*wb ----------------------
__global__ __launch_bounds__(256, 2) void k_mma_g1(int cur) {
    extern __shared__ __align__(128) char dsm[];
    const uint32_t sb0 = smem_to_u32(dsm);
    const int tid = threadIdx.x, lane = tid & 31, wid = tid >> 5;
    const int wmi = wid >> 2, wni = wid & 3;
    const int nt = blockIdx.x, sp = blockIdx.y, b = blockIdx.z;
    const __nv_bfloat16* Ah = g_h16h[cur] + (size_t)b * CC * NN + (size_t)sp * KSP;
    const __nv_bfloat16* Al = g_h16l[cur] + (size_t)b * CC * NN + (size_t)sp * KSP;
    const __nv_bfloat16* Bh = g_wb16h + ((size_t)b * 256 + nt * 128) * NN + (size_t)sp * KSP;
    const __nv_bfloat16* Bl = g_wb16l + ((size_t)b * 256 + nt * 128) * NN + (size_t)sp * KSP;
    float acc[4][4][4] = {};
    const int niter = KSP / 32;    // 32
    fill_g1(sb0, 0, tid, Ah, Al, Bh, Bl);
    CP_COMMIT;
    fill_g1(sb0 + STG, 32, tid, Ah, Al, Bh, Bl);
    CP_COMMIT;
    int fs = 2;
    for (int it = 0; it < niter; ++it) {
        CP_WAIT1;
        __syncthreads();
        if (it + 2 < niter) {
            fill_g1(sb0 + (uint32_t)fs * STG, (it + 2) * 32, tid, Ah, Al, Bh, Bl);
        }
        CP_COMMIT;
        const int cs = (fs + 1 == NSTAGE) ? 0 : fs + 1;
        compute_chunk<false>(sb0 + (uint32_t)((it % NSTAGE)) * STG, wmi, wni, lane, acc);
        fs = cs;
    }
    float* pp = g_part + (((size_t)sp * BB + b) * CC) * JP + nt * 128;
    #pragma unroll
    for (int mi = 0; mi < 4; mi++) {
        #pragma unroll
        for (int ni = 0; ni < 4; ni++) {
            const int m = wmi * 64 + mi * 16 + (lane >> 2);
            const int n = wni * 32 + ni * 8 + (lane & 3) * 2;
            *(float2*)&pp[(size_t)m * JP + n]       = make_float2(acc[mi][ni][0], acc[mi][ni][1]);
            *(float2*)&pp[(size_t)(m + 8) * JP + n] = make_float2(acc[mi][ni][2], acc[mi][ni][3]);
        }
    }
}

// ---------------- G2: D[o=128][x=128-tile] = sum_j A*[bases;h] ---------------
// epilogue: + conv_b + f0*mask, gelu, bf16 split write, x0 partials
__global__ __launch_bounds__(256, 2) void k_mma_g2(int cur, int nxt,
                                                   const float* __restrict__ conv_b,
                                                   int l, int dogelu, int dox0) {
    extern __shared__ __align__(128) char dsm[];
    __shared__ float scb[128];
    __shared__ float s_wm[128];
    __shared__ float s_f0[128];
    __shared__ float s_mask[128];
    __shared__ float s_part[128][16];
    const uint32_t sb0 = smem_to_u32(dsm);
    const int tid = threadIdx.x, lane = tid & 31, wid = tid >> 5;
    const int wmi = wid >> 2, wni = wid & 3;
    const int xt = blockIdx.x, b = blockIdx.y;
    if (tid < 128) {
        scb[tid] = conv_b[l * CC + tid];
        s_wm[tid] = g_wm[(size_t)b * NN + (size_t)xt * 128 + tid];
        s_f0[tid] = g_f0[b * CC + tid];
        s_mask[tid] = g_mask[(size_t)b * NN + (size_t)xt * 128 + tid];
    }
    const __nv_bfloat16* Ah = g_Ah + (size_t)b * CC * KA;
    const __nv_bfloat16* Al = g_Al + (size_t)b * CC * KA;
    const __nv_bfloat16* Bbh = g_b16h + (size_t)b * 256 * NN + (size_t)xt * 128;
    const __nv_bfloat16* Bbl = g_b16l + (size_t)b * 256 * NN + (size_t)xt * 128;
    const __nv_bfloat16* Hh = g_h16h[cur] + (size_t)b * CC * NN + (size_t)xt * 128;
    const __nv_bfloat16* Hl = g_h16l[cur] + (size_t)b * CC * NN + (size_t)xt * 128;
    float acc[4][4][4] = {};
    const int niter = KA / 32;   // 12
    fill_g2(sb0, 0, tid, Ah, Al, Bbh, Bbl, Hh, Hl);
    CP_COMMIT;
    fill_g2(sb0 + STG, 32, tid, Ah, Al, Bbh, Bbl, Hh, Hl);
    CP_COMMIT;
    int fs = 2;
    for (int it = 0; it < niter; ++it) {
        CP_WAIT1;
        __syncthreads();
        if (it + 2 < niter) {
            fill_g2(sb0 + (uint32_t)fs * STG, (it + 2) * 32, tid, Ah, Al, Bbh, Bbl, Hh, Hl);
        }
        CP_COMMIT;
        const int cs = (fs + 1 == NSTAGE) ? 0 : fs + 1;
        compute_chunk<true>(sb0 + (uint32_t)((it % NSTAGE)) * STG, wmi, wni, lane, acc);
        fs = cs;
    }
    __syncthreads();
    __nv_bfloat16* hh = g_h16h[nxt] + (size_t)b * CC * NN + (size_t)xt * 128;
    __nv_bfloat16* hl = g_h16l[nxt] + (size_t)b * CC * NN + (size_t)xt * 128;
    float sx[8] = {};
    #pragma unroll
    for (int mi = 0; mi < 4; mi++) {
        #pragma unroll
        for (int ni = 0; ni < 4; ni++) {
            const int n = wni * 32 + ni * 8 + (lane & 3) * 2;
            #pragma unroll
            for (int half = 0; half < 2; half++) {
                const int o = wmi * 64 + mi * 16 + (lane >> 2) + half * 8;
                const float f0o = s_f0[o];
                float v0 = acc[mi][ni][half * 2 + 0] + scb[o] + f0o * s_mask[n];
                float v1 = acc[mi][ni][half * 2 + 1] + scb[o] + f0o * s_mask[n + 1];
                if (dogelu) { v0 = gelu_f(v0); v1 = gelu_f(v1); }
                uint32_t pl, ph = pack_split2(v0, v1, &pl);
                *(uint32_t*)&hh[(size_t)o * NN + n] = ph;
                *(uint32_t*)&hl[(size_t)o * NN + n] = pl;
                if (dox0) {
                    sx[mi * 2 + half] = fmaf(v0, s_wm[n], sx[mi * 2 + half]);
                    sx[mi * 2 + half] = fmaf(v1, s_wm[n + 1], sx[mi * 2 + half]);
                }
            }
        }
    }
    if (dox0) {
        const int slot = wni * 4 + (lane & 3);
        #pragma unroll
        for (int mi = 0; mi < 4; mi++)
            #pragma unroll
            for (int half = 0; half < 2; half++) {
                const int o = wmi * 64 + mi * 16 + (lane >> 2) + half * 8;
                s_part[o][slot] = sx[mi * 2 + half];
            }
        __syncthreads();
        if (tid < 128) {
            float s = 0.f;
            #pragma unroll
            for (int q = 0; q < 16; q++) s += s_part[tid][q];
            g_x0p[xt][b * CC + tid] = s;
        }
    }
}

// ---------------- final MLP as MMA: y[x] = fc2 . gelu(fc1T @ h + b1) + b2 ----
__global__ __launch_bounds__(256, 2) void k_final_mma(const float* __restrict__ fc1_b,
                                                      const float* __restrict__ fc2_w,
                                                      const float* __restrict__ fc2_b,
                                                      float* __restrict__ out) {
    extern __shared__ __align__(128) char dsm[];
    __shared__ float s_fb[128];
    __shared__ float s_w2[128];
    __shared__ float s_red[128][17];
    const uint32_t sb0 = smem_to_u32(dsm);
    const int tid = threadIdx.x, lane = tid & 31, wid = tid >> 5;
    const int wmi = wid >> 2, wni = wid & 3;
    const int xt = blockIdx.x, b = blockIdx.y;
    if (tid < 128) { s_fb[tid] = fc1_b[tid]; s_w2[tid] = fc2_w[tid]; }
    const __nv_bfloat16* Hh = g_h16h[0] + (size_t)b * CC * NN + (size_t)xt * 128;
    const __nv_bfloat16* Hl = g_h16l[0] + (size_t)b * CC * NN + (size_t)xt * 128;
    float acc[4][4][4] = {};
    const int niter = CC / 32;   // 4
    fill_fc(sb0, 0, tid, Hh, Hl);
    CP_COMMIT;
    fill_fc(sb0 + STG, 32, tid, Hh, Hl);
    CP_COMMIT;
    int fs = 2;
    for (int it = 0; it < niter; ++it) {
        CP_WAIT1;
        __syncthreads();
        if (it + 2 < niter) {
            fill_fc(sb0 + (uint32_t)fs * STG, (it + 2) * 32, tid, Hh, Hl);
        }
        CP_COMMIT;
        const int cs = (fs + 1 == NSTAGE) ? 0 : fs + 1;
        compute_chunk<true>(sb0 + (uint32_t)((it % NSTAGE)) * STG, wmi, wni, lane, acc);
        fs = cs;
    }
    __syncthreads();
    float xs[8] = {};
    #pragma unroll
    for (int mi = 0; mi < 4; mi++) {
        #pragma unroll
        for (int ni = 0; ni < 4; ni++) {
            #pragma unroll
            for (int half = 0; half < 2; half++) {
                const int f = wmi * 64 + mi * 16 + (lane >> 2) + half * 8;
                const float w2 = s_w2[f], b1 = s_fb[f];
                xs[ni * 2 + 0] = fmaf(w2, gelu_f(acc[mi][ni][half * 2 + 0] + b1), xs[ni * 2 + 0]);
                xs[ni * 2 + 1] = fmaf(w2, gelu_f(acc[mi][ni][half * 2 + 1] + b1), xs[ni * 2 + 1]);
            }
        }
    }
    const int slot = wmi * 8 + (lane >> 2);
    #pragma unroll
    for (int ni = 0; ni < 4; ni++) {
        #pragma unroll
        for (int p = 0; p < 2; p++) {
            const int x = wni * 32 + ni * 8 + (lane & 3) * 2 + p;
            s_red[x][slot] = xs[ni * 2 + p];
        }
    }
    __syncthreads();
    if (tid < 128) {
        float s = fc2_b[0];
        #pragma unroll
        for (int q = 0; q < 16; q++) s += s_red[tid][q];
        out[(size_t)b * NN + (size_t)xt * 128 + tid] = s;
    }
}

// ---------------- weight transpose (once) ------------------------------------
__global__ void k_wtrans(const float* __restrict__ wc, const float* __restrict__ ws) {
    __shared__ float sm[32][33];
    const int tile = blockIdx.x;
    const int o0 = (tile >> 2) * 32, k0 = (tile & 3) * 32;
    const int i = blockIdx.y, l = blockIdx.z;
    const float scale = 1.0f / 8192.0f;
    for (int w = 0; w < 2; w++) {
        const float* src = w ? ws : wc;
        float* dst = w ? g_wst : g_wct;
        #pragma unroll
        for (int s = 0; s < 4; s++) {
            int oo = threadIdx.y + 8 * s, kk = threadIdx.x;
            sm[oo][kk] = src[(((size_t)l * CC + i) * CC + (o0 + oo)) * KK + (k0 + kk)] * scale;
        }
        __syncthreads();
        #pragma unroll
        for (int s = 0; s < 4; s++) {
            int kk = threadIdx.y + 8 * s, oo = threadIdx.x;
            dst[(((size_t)l * KK + (k0 + kk)) * CC + i) * CC + (o0 + oo)] = sm[oo][kk];
        }
        __syncthreads();
    }
}

// ---------------- fc1^T split prep (once, tiny) -------------------------------
__global__ void k_prepfc(const float* __restrict__ fc1_w) {
    const int f = blockIdx.x, c = threadIdx.x;
    __nv_bfloat16 hi, lo;
    split_bf16(fc1_w[c * CC + f], &hi, &lo);
    g_fc1h[f * CC + c] = hi;
    g_fc1l[f * CC + c] = lo;
}

// ---------------- precompute: bases16, wb16, wm, mask, h0 + fused x0 ---------
// grid BB*NN/512 CTAs; CTA covers 512 consecutive x within one batch.
// x0 partial slot = blockIdx.x & 15 (16 partials per batch), npart=16 in k_mid.
__global__ __launch_bounds__(256) void k_pre(const float* __restrict__ xin,
                                             const float* __restrict__ modes,
                                             const float* __restrict__ fc0_w,
                                             const float* __restrict__ fc0_b) {
    __shared__ float sm_modes[256];
    __shared__ float sm_w[384];
    __shared__ float sm_b[128];
    __shared__ float s_x0w[128][9];   // [c][warp], padded
    const int t = threadIdx.x;
    const int lane = t & 31, wid = t >> 5;
    sm_modes[t] = modes[t];
    sm_w[t] = fc0_w[t];
    if (t < 128) { sm_w[256 + t] = fc0_w[256 + t]; sm_b[t] = fc0_b[t]; }
    __syncthreads();

    const int gid = (blockIdx.x * 256 + t) * 2;       // even x pair over B*N
    const int b = gid / NN, xx = gid - b * NN;
    const float* xr = xin + (size_t)gid * 7;
    const float p0i0 = xr[0], p0i1 = xr[1], p0i2 = xr[2];
    const float p0d0 = xr[3], p0d1 = xr[4], p0w = xr[5], p0m = xr[6];
    const float p1i0 = xr[7], p1i1 = xr[8], p1i2 = xr[9];
    const float p1d0 = xr[10], p1d1 = xr[11], p1w = xr[12], p1m = xr[13];

    const float wsz0 = p0w * (float)NN, wsz1 = p1w * (float)NN;
    const float wm0 = wsz0 * p0m, wm1 = wsz1 * p1m;
    *(float2*)&g_wm[gid] = make_float2(wm0, wm1);
    *(float2*)&g_mask[gid] = make_float2(p0m, p1m);

    uint32_t* bh = (uint32_t*)(g_b16h + (size_t)b * 256 * NN + xx);
    uint32_t* bl = (uint32_t*)(g_b16l + (size_t)b * 256 * NN + xx);
    uint32_t* wbh = (uint32_t*)(g_wb16h + (size_t)b * 256 * NN + xx);
    uint32_t* wbl = (uint32_t*)(g_wb16l + (size_t)b * 256 * NN + xx);
    #pragma unroll 2
    for (int k = 0; k < KK; k++) {
        const float m0 = sm_modes[2 * k], m1 = sm_modes[2 * k + 1];
        float s0, c0, s1, c1;
        fast_sincos(fmaf(p0d0, m0, p0d1 * m1), &s0, &c0);
        fast_sincos(fmaf(p1d0, m0, p1d1 * m1), &s1, &c1);
        const float cm0 = c0 * p0m, sm0 = s0 * p0m;
        const float cm1 = c1 * p1m, sm1 = s1 * p1m;
        uint32_t lo, hi;
        hi = pack_split2(cm0, cm1, &lo);
        bh[(size_t)k * (NN / 2)] = hi; bl[(size_t)k * (NN / 2)] = lo;
        hi = pack_split2(sm0, sm1, &lo);
        bh[(size_t)(128 + k) * (NN / 2)] = hi; bl[(size_t)(128 + k) * (NN / 2)] = lo;
        hi = pack_split2(cm0 * wsz0, cm1 * wsz1, &lo);
        wbh[(size_t)k * (NN / 2)] = hi; wbl[(size_t)k * (NN / 2)] = lo;
        hi = pack_split2(sm0 * wsz0, sm1 * wsz1, &lo);
        wbh[(size_t)(128 + k) * (NN / 2)] = hi; wbl[(size_t)(128 + k) * (NN / 2)] = lo;
    }
    uint32_t* h16h = (uint32_t*)(g_h16h[0] + (size_t)b * CC * NN + xx);
    uint32_t* h16l = (uint32_t*)(g_h16l[0] + (size_t)b * CC * NN + xx);
    #pragma unroll 4
    for (int c = 0; c < CC; c++) {
        float v0 = sm_b[c], v1 = sm_b[c];
        v0 = fmaf(p0i0, sm_w[c], v0);
        v0 = fmaf(p0i1, sm_w[128 + c], v0);
        v0 = fmaf(p0i2, sm_w[256 + c], v0);
        v1 = fmaf(p1i0, sm_w[c], v1);
        v1 = fmaf(p1i1, sm_w[128 + c], v1);
        v1 = fmaf(p1i2, sm_w[256 + c], v1);
        uint32_t lo, hi = pack_split2(v0, v1, &lo);
        h16h[(size_t)c * (NN / 2)] = hi;
        h16l[(size_t)c * (NN / 2)] = lo;
        // fused x0 partial: warp-reduce v0*wm0 + v1*wm1 (deterministic tree)
        float xc = fmaf(v0, wm0, v1 * wm1);
        #pragma unroll
        for (int off = 16; off; off >>= 1) xc += __shfl_xor_sync(0xffffffffu, xc, off);
        if (lane == 0) s_x0w[c][wid] = xc;
    }
    __syncthreads();
    if (t < 128) {
        float s = 0.f;
        #pragma unroll
        for (int q = 0; q < 8; q++) s += s_x0w[t][q];
        g_x0p[blockIdx.x & 15][b * CC + t] = s;
    }
}

// ---------------- k_mid: fused fmix (bx<128) + f0/conv (bx>=128) --------------
__global__ __launch_bounds__(128) void k_mid(const float* __restrict__ w0,
                                             const float* __restrict__ conv_w,
                                             int l, int npart) {
    const int t = threadIdx.x;
    if (blockIdx.x < 128) {
        const int k = blockIdx.x;
        const int bh = blockIdx.y * 8;
        __shared__ float xc_s[128][8];
        __shared__ float xs_s[128][8];
        #pragma unroll
        for (int b = 0; b < 8; b++) {
            float sc = 0.f, ss = 0.f;
            #pragma unroll
            for (int s = 0; s < NSPLIT; s++) {
                const float* pp = g_part + (((size_t)s * BB + bh + b) * CC + t) * JP;
                sc += pp[k];
                ss += pp[128 + k];
            }
            xc_s[t][b] = sc;
            xs_s[t][b] = -ss;
        }
        __syncthreads();
        float fc[8] = {}, fs[8] = {};
        const float* wcp = g_wct + ((size_t)(l * KK + k)) * CC * CC + t;
        const float* wsp = g_wst + ((size_t)(l * KK + k)) * CC * CC + t;
        #pragma unroll 4
        for (int i = 0; i < 128; i++) {
            const float wcv = wcp[(size_t)i * CC], wsv = wsp[(size_t)i * CC];
            #pragma unroll
            for (int b = 0; b < 8; b++) {
                const float cv = xc_s[i][b], sv = xs_s[i][b];
                fc[b] = fmaf(cv, wcv, fc[b]); fc[b] = fmaf(-sv, wsv, fc[b]);
                fs[b] = fmaf(sv, wcv, fs[b]); fs[b] = fmaf(cv, wsv, fs[b]);
            }
        }
        #pragma unroll
        for (int b = 0; b < 8; b++) {
            const size_t base = ((size_t)(bh + b) * CC + t) * KA;
            __nv_bfloat16 hi, lo;
            split_bf16(2.f * fc[b], &hi, &lo);
            g_Ah[base + k] = hi; g_Al[base + k] = lo;
            split_bf16(-2.f * fs[b], &hi, &lo);
            g_Ah[base + 128 + k] = hi; g_Al[base + 128 + k] = lo;
        }
    } else {
        const int b = (blockIdx.x - 128) + blockIdx.y * 8;
        __shared__ float x0s[128];
        float s = 0.f;
        for (int p = 0; p < npart; p++) s += g_x0p[p][b * CC + t];
        x0s[t] = s;
        __syncthreads();
        float f0 = 0.f;
        const float* w0p = w0 + (size_t)l * CC * CC;
        #pragma unroll 8
        for (int i = 0; i < 128; i++) f0 = fmaf(x0s[i], w0p[(size_t)i * CC + t], f0);
        g_f0[b * CC + t] = f0 * (1.0f / 8192.0f);     // fp32 rank-1 term (epilogue)
        const size_t base = ((size_t)b * CC + t) * KA;
        __nv_bfloat16 hi, lo;
        const float* cw = conv_w + ((size_t)(l * CC) + t) * CC;
        #pragma unroll 8
        for (int i = 0; i < 128; i++) {
            split_bf16(cw[i], &hi, &lo);
            g_Ah[base + 256 + i] = hi; g_Al[base + 256 + i] = lo;
        }
    }
}

// ---------------- launch -------------------------------------------------------
extern "C" void kernel_launch(void* const* d_in, const int* in_sizes, int n_in,
                              void* d_out, int out_size) {
    const float* x      = (const float*)d_in[0];
    const float* modes  = (const float*)d_in[1];
    const float* fc0_w  = (const float*)d_in[2];
    const float* fc0_b  = (const float*)d_in[3];
    const float* wc     = (const float*)d_in[4];
    const float* ws     = (const float*)d_in[5];
    const float* w0     = (const float*)d_in[6];
    const float* conv_w = (const float*)d_in[7];
    const float* conv_b = (const float*)d_in[8];
    const float* fc1_w  = (const float*)d_in[9];
    const float* fc1_b  = (const float*)d_in[10];
    const float* fc2_w  = (const float*)d_in[11];
    const float* fc2_b  = (const float*)d_in[12];
    float* out = (float*)d_out;

    const int smem = NSTAGE * (int)STG;   // 96KB
    cudaFuncSetAttribute(k_mma_g1, cudaFuncAttributeMaxDynamicSharedMemorySize, smem);
    cudaFuncSetAttribute(k_mma_g2, cudaFuncAttributeMaxDynamicSharedMemorySize, smem);
    cudaFuncSetAttribute(k_final_mma, cudaFuncAttributeMaxDynamicSharedMemorySize, smem);

    k_wtrans<<<dim3(16, 128, 4), dim3(32, 8)>>>(wc, ws);
    k_prepfc<<<CC, CC>>>(fc1_w);
    k_pre<<<(BB * NN) / 512, 256>>>(x, modes, fc0_w, fc0_b);
    for (int l = 0; l < LL; l++) {
        const int cur = l & 1, nxt = cur ^ 1;
        k_mma_g1<<<dim3(2, NSPLIT, BB), 256, smem>>>(cur);
        k_mid<<<dim3(136, 2), 128>>>(w0, conv_w, l, (l == 0) ? 16 : 64);
        k_mma_g2<<<dim3(NN / 128, BB), 256, smem>>>(cur, nxt, conv_b, l,
                                                    (l < LL - 1) ? 1 : 0,
                                                    (l < LL - 1) ? 1 : 0);
    }
    k_final_mma<<<dim3(NN / 128, BB), 256, smem>>>(fc1_b, fc2_w, fc2_b, out);
}

// round 16
// speedup vs baseline: 1.0328x; 1.0327x over previous
#include <cuda_runtime.h>
#include <cuda_bf16.h>
#include <math.h>
#include <stdint.h>

#define BB 16
#define NN 8192
#define CC 128
#define KK 128
#define LL 4
#define JP 256
#define KA 384            // G2 K: [2fc(128), -2fs(128), conv_w(128)] = 12*32, no padding
#define NSPLIT 8
#define KSP (NN / NSPLIT) // 1024

// ---------------- scratch (device globals) ----------------------------------
__device__ float g_wm[BB * NN];                                 // weights*size*mask
__device__ float g_mask[BB * NN];                               // mask
__device__ float g_f0[BB * CC];                                 // f_0/size (fp32, rank-1 term)
__device__ __nv_bfloat16 g_h16h[2][(size_t)BB * CC * NN];       // h split hi/lo ping-pong
__device__ __nv_bfloat16 g_h16l[2][(size_t)BB * CC * NN];
__device__ __nv_bfloat16 g_wb16h[(size_t)BB * 256 * NN];        // bases*wsz split [b][j][x]
__device__ __nv_bfloat16 g_wb16l[(size_t)BB * 256 * NN];
__device__ __nv_bfloat16 g_b16h[(size_t)BB * 256 * NN];         // bases split [b][j][x]
__device__ __nv_bfloat16 g_b16l[(size_t)BB * 256 * NN];
__device__ float g_part[(size_t)NSPLIT * BB * CC * JP];         // G1 split partials
__device__ float g_x0p[64][BB * CC];                            // x0 partials
__device__ __nv_bfloat16 g_Ah[(size_t)BB * CC * KA];            // G2 A split [b][o][j]
__device__ __nv_bfloat16 g_Al[(size_t)BB * CC * KA];
__device__ __nv_bfloat16 g_fc1h[CC * CC];                       // fc1^T split [f][c]
__device__ __nv_bfloat16 g_fc1l[CC * CC];
__device__ float g_wct[(size_t)LL * KK * CC * CC];
__device__ float g_wst[(size_t)LL * KK * CC * CC];

__device__ __forceinline__ float gelu_f(float v) {
    return 0.5f * v * (1.0f + erff(v * 0.70710678118654752f));
}
__device__ __forceinline__ void split_bf16(float v, __nv_bfloat16* hi, __nv_bfloat16* lo) {
    __nv_bfloat16 h = __float2bfloat16(v);
    *hi = h;
    *lo = __float2bfloat16(v - __bfloat162float(h));
}
// fast packed split: hi = rn(v), lo = rn(v - hi), 2 lanes at once
__device__ __forceinline__ uint32_t pack_split2(float v0, float v1, uint32_t* lo_out) {
    uint32_t ph;
    asm("cvt.rn.bf16x2.f32 %0, %1, %2;" : "=r"(ph) : "f"(v1), "f"(v0));
    const float h0 = __uint_as_float(ph << 16);
    const float h1 = __uint_as_float(ph & 0xFFFF0000u);
    uint32_t pl;
    asm("cvt.rn.bf16x2.f32 %0, %1, %2;" : "=r"(pl) : "f"(v1 - h1), "f"(v0 - h0));
    *lo_out = pl;
    return ph;
}
__device__ __forceinline__ uint32_t smem_to_u32(const void* p) {
    uint32_t a;
    asm("{ .reg .u64 t; cvta.to.shared.u64 t, %1; cvt.u32.u64 %0, t; }" : "=r"(a) : "l"(p));
    return a;
}
__device__ __forceinline__ float2 rec2(uint32_t h, uint32_t l) {
    __nv_bfloat162 hh = *(__nv_bfloat162*)&h;
    __nv_bfloat162 ll = *(__nv_bfloat162*)&l;
    return make_float2(__bfloat162float(hh.x) + __bfloat162float(ll.x),
                       __bfloat162float(hh.y) + __bfloat162float(ll.y));
}

// ---------------- FMA-pipe sincos (no MUFU): Cody-Waite + minimax ------------
__device__ __forceinline__ void fast_sincos(float t, float* sout, float* cout) {
    const float fn = rintf(t * 0.636619772f);       // 2/pi
    const int n = (int)fn;
    float r = fmaf(fn, -1.57079637e0f, t);          // pi/2 hi
    r = fmaf(fn, 4.37113883e-8f, r);                // pi/2 lo correction
    const float r2 = r * r;
    float ps = fmaf(fmaf(-1.9515296e-4f, r2, 8.3321608e-3f), r2, -1.6666654e-1f);
    ps = fmaf(ps * r2, r, r);                       // sin(r)
    float pc = fmaf(fmaf(2.44331571e-5f, r2, -1.38873163e-3f), r2, 4.16666456e-2f);
    pc = fmaf(pc, r2 * r2, fmaf(-0.5f, r2, 1.0f));  // cos(r)
    const int q = n & 3;
    float s = (q & 1) ? pc : ps;
    float c = (q & 1) ? ps : pc;
    if ((q + 1) & 2) c = -c;
    if (q & 2) s = -s;
    *sout = s;
    *cout = c;
}

// ---------------- mma.sync / ldmatrix / cp.async primitives -----------------
__device__ __forceinline__ void ldsm4(uint32_t (&d)[4], uint32_t a) {
    asm volatile("ldmatrix.sync.aligned.m8n8.x4.shared.b16 {%0,%1,%2,%3}, [%4];"
        : "=r"(d[0]), "=r"(d[1]), "=r"(d[2]), "=r"(d[3]) : "r"(a));
}
__device__ __forceinline__ void ldsm4t(uint32_t (&d)[4], uint32_t a) {
    asm volatile("ldmatrix.sync.aligned.m8n8.x4.trans.shared.b16 {%0,%1,%2,%3}, [%4];"
        : "=r"(d[0]), "=r"(d[1]), "=r"(d[2]), "=r"(d[3]) : "r"(a));
}
__device__ __forceinline__ void mma16816(float (&c)[4], const uint32_t (&a)[4], const uint32_t (&b)[2]) {
    asm volatile("mma.sync.aligned.m16n8k16.row.col.f32.bf16.bf16.f32 "
        "{%0,%1,%2,%3},{%4,%5,%6,%7},{%8,%9},{%0,%1,%2,%3};"
        : "+f"(c[0]), "+f"(c[1]), "+f"(c[2]), "+f"(c[3])
        : "r"(a[0]), "r"(a[1]), "r"(a[2]), "r"(a[3]), "r"(b[0]), "r"(b[1]));
}
__device__ __forceinline__ void cpasync16(uint32_t s, const void* g) {
    asm volatile("cp.async.cg.shared.global [%0], [%1], 16;" :: "r"(s), "l"(g));
}
#define CP_COMMIT asm volatile("cp.async.commit_group;" ::: "memory")
#define CP_WAIT1  asm volatile("cp.async.wait_group 1;" ::: "memory")

// stage layout (bytes): Ah @0, Al @8192, Bh @16384, Bl @24576; stage = 32KB, 3 stages
#define STG 32768u
#define NSTAGE 3

__device__ __forceinline__ uint32_t swzA(int r, int c) {
    return (uint32_t)(r * 64 + ((c ^ ((r >> 1) & 3)) << 4));
}
__device__ __forceinline__ uint32_t swzB(int r, int c) {
    return (uint32_t)(r * 256 + ((c ^ (r & 7)) << 4));
}

// ---------------- stage fills (256-thread CTA) --------------------------------
__device__ __forceinline__ void fill_g1(uint32_t sb, int k0, int tid,
    const __nv_bfloat16* Ah, const __nv_bfloat16* Al,
    const __nv_bfloat16* Bh, const __nv_bfloat16* Bl)
{
    #pragma unroll
    for (int q = 0; q < 8; q++) {
        const int op = q >> 1;
        const int local = ((q & 1) << 8) + tid;
        const int r = local >> 2, c = local & 3;
        const __nv_bfloat16* base = (op == 0) ? Ah : (op == 1) ? Al : (op == 2) ? Bh : Bl;
        cpasync16(sb + (uint32_t)op * 8192u + swzA(r, c),
                  base + (size_t)r * NN + k0 + c * 8);
    }
}
__device__ __forceinline__ void fill_g2(uint32_t sb, int k0, int tid,
    const __nv_bfloat16* Ah, const __nv_bfloat16* Al,
    const __nv_bfloat16* Bbh, const __nv_bfloat16* Bbl,
    const __nv_bfloat16* Hh, const __nv_bfloat16* Hl)
{
    #pragma unroll
    for (int q = 0; q < 8; q++) {
        const int op = q >> 1;
        const int local = ((q & 1) << 8) + tid;
        if (q < 4) {
            const int r = local >> 2, c = local & 3;
            const __nv_bfloat16* base = (op == 0) ? Ah : Al;
            cpasync16(sb + (uint32_t)op * 8192u + swzA(r, c),
                      base + (size_t)r * KA + k0 + c * 8);
        } else {
            const int r = local >> 4, c = local & 15;
            const int jg = k0 + r;
            const bool ishi = (q < 6);
            const __nv_bfloat16* src = (jg < 256)
                ? (ishi ? Bbh : Bbl) + (size_t)jg * NN
                : (ishi ? Hh : Hl) + (size_t)(jg - 256) * NN;
            cpasync16(sb + (uint32_t)op * 8192u + swzB(r, c), src + c * 8);
        }
    }
}
__device__ __forceinline__ void fill_fc(uint32_t sb, int k0, int tid,
    const __nv_bfloat16* Hh, const __nv_bfloat16* Hl)
{
    #pragma unroll
    for (int q = 0; q < 8; q++) {
        const int op = q >> 1;
        const int local = ((q & 1) << 8) + tid;
        if (q < 4) {
            const int r = local >> 2, c = local & 3;
            const __nv_bfloat16* base = (op == 0) ? g_fc1h : g_fc1l;
            cpasync16(sb + (uint32_t)op * 8192u + swzA(r, c),
                      base + (size_t)r * CC + k0 + c * 8);
        } else {
            const int r = local >> 4, c = local & 15;
            const __nv_bfloat16* src = ((q < 6) ? Hh : Hl) + (size_t)(k0 + r) * NN;
            cpasync16(sb + (uint32_t)op * 8192u + swzB(r, c), src + c * 8);
        }
    }
}

// ---------------- warp compute: one k32 chunk, 8 warps 64x32 tiles ------------
// (R10 form — frozen; B hoisted per k16, A loaded per-mi)
template<bool BT>
__device__ __forceinline__ void compute_chunk(uint32_t sb, int wmi, int wni, int lane,
                                              float (&acc)[4][4][4]) {
    #pragma unroll
    for (int k16 = 0; k16 < 2; k16++) {
        uint32_t bh[4][2], bl[4][2];
        #pragma unroll
        for (int g = 0; g < 2; g++) {
            uint32_t t[4], u[4];
            if (!BT) {
                const int r = wni * 32 + g * 16 + (lane & 15);
                const int c = k16 * 2 + (lane >> 4);
                const uint32_t bd = sb + 16384u + swzA(r, c);
                ldsm4(t, bd);
                ldsm4(u, bd + 8192u);
                bh[g*2+0][0] = t[0]; bh[g*2+0][1] = t[2];
                bh[g*2+1][0] = t[1]; bh[g*2+1][1] = t[3];
                bl[g*2+0][0] = u[0]; bl[g*2+0][1] = u[2];
                bl[g*2+1][0] = u[1]; bl[g*2+1][1] = u[3];
            } else {
                const int r = k16 * 16 + (lane & 15);
                const int c = wni * 4 + g * 2 + (lane >> 4);
                const uint32_t bd = sb + 16384u + swzB(r, c);
                ldsm4t(t, bd);
                ldsm4t(u, bd + 8192u);
                bh[g*2+0][0] = t[0]; bh[g*2+0][1] = t[1];
                bh[g*2+1][0] = t[2]; bh[g*2+1][1] = t[3];
                bl[g*2+0][0] = u[0]; bl[g*2+0][1] = u[1];
                bl[g*2+1][0] = u[2]; bl[g*2+1][1] = u[3];
            }
        }
        #pragma unroll
        for (int mi = 0; mi < 4; mi++) {
            uint32_t ah[4], al[4];
            {
                const int r = wmi * 64 + mi * 16 + (lane & 15);
                const int c = k16 * 2 + (lane >> 4);
                const uint32_t ad = sb + swzA(r, c);
                ldsm4(ah, ad);
                ldsm4(al, ad + 8192u);
            }
            #pragma unroll
            for (int ni = 0; ni < 4; ni++) {
                mma16816(acc[mi][ni], ah, bh[ni]);
                mma16816(acc[mi][ni], ah, bl[ni]);
                mma16816(acc[mi][ni], al, bh[ni]);
            }
        }
    }
}

// ---------------- G1 + fused f0/conv plane ------------------------------------
// grid (2, NSPLIT, BB+1). z < BB: G1 GEMM. z == BB: 2*8=16 blocks run the
// f0/conv half of the old k_mid (depends only on g_x0p / conv_w, NOT on G1).
__global__ __launch_bounds__(256, 2) void k_mma_g1(int cur, const float* __restrict__ w0,
                                                   const float* __restrict__ conv_w,
                                                   int l, int npart) {
    extern __shared__ __align__(128) char dsm[];
    const uint32_t sb0 = smem_to_u32(dsm);
    const int tid = threadIdx.x, lane = tid & 31, wid = tid >> 5;

    if (blockIdx.z == BB) {
        // ---- f0 + conv rows of A (independent of G1) ----
        float* x0s = (float*)dsm;                     // 128 floats in dynamic smem
        const int b = blockIdx.x * 8 + blockIdx.y;
        const int t = tid;
        if (t < 128) {
            float s = 0.f;
            for (int p = 0; p < npart; p++) s += g_x0p[p][b * CC + t];
            x0s[t] = s;
        }
        __syncthreads();
        if (t < 128) {
            float f0 = 0.f;
            const float* w0p = w0 + (size_t)l * CC * CC;
            #pragma unroll 8
            for (int i = 0; i < 128; i++) f0 = fmaf(x0s[i], w0p[(size_t)i * CC + t], f0);
            g_f0[b * CC + t] = f0 * (1.0f / 8192.0f);
            const size_t base = ((size_t)b * CC + t) * KA;
            __nv_bfloat16 hi, lo;
            const float* cw = conv_w + ((size_t)(l * CC) + t) * CC;
            #pragma unroll 8
            for (int i = 0; i < 128; i++) {
                split_bf16(cw[i], &hi, &lo);
                g_Ah[base + 256 + i] = hi; g_Al[base + 256 + i] = lo;
            }
        }
        return;
    }

    // ---- G1 GEMM (frozen R10 loop) ----
    const int wmi = wid >> 2, wni = wid & 3;
    const int nt = blockIdx.x, sp = blockIdx.y, b = blockIdx.z;
    const __nv_bfloat16* Ah = g_h16h[cur] + (size_t)b * CC * NN + (size_t)sp * KSP;
    const __nv_bfloat16* Al = g_h16l[cur] + (size_t)b * CC * NN + (size_t)sp * KSP;
    const __nv_bfloat16* Bh = g_wb16h + ((size_t)b * 256 + nt * 128) * NN + (size_t)sp * KSP;
    const __nv_bfloat16* Bl = g_wb16l + ((size_t)b * 256 + nt * 128) * NN + (size_t)sp * KSP;
    float acc[4][4][4] = {};
    const int niter = KSP / 32;    // 32
    fill_g1(sb0, 0, tid, Ah, Al, Bh, Bl);
    CP_COMMIT;
    fill_g1(sb0 + STG, 32, tid, Ah, Al, Bh, Bl);
    CP_COMMIT;
    int fs = 2;
    for (int it = 0; it < niter; ++it) {
        CP_WAIT1;
        __syncthreads();
        if (it + 2 < niter) {
            fill_g1(sb0 + (uint32_t)fs * STG, (it + 2) * 32, tid, Ah, Al, Bh, Bl);
        }
        CP_COMMIT;
        const int cs = (fs + 1 == NSTAGE) ? 0 : fs + 1;
        compute_chunk<false>(sb0 + (uint32_t)((it % NSTAGE)) * STG, wmi, wni, lane, acc);
        fs = cs;
    }
    float* pp = g_part + (((size_t)sp * BB + b) * CC) * JP + nt * 128;
    #pragma unroll
    for (int mi = 0; mi < 4; mi++) {
        #pragma unroll
        for (int ni = 0; ni < 4; ni++) {
            const int m = wmi * 64 + mi * 16 + (lane >> 2);
            const int n = wni * 32 + ni * 8 + (lane & 3) * 2;
            *(float2*)&pp[(size_t)m * JP + n]       = make_float2(acc[mi][ni][0], acc[mi][ni][1]);
            *(float2*)&pp[(size_t)(m + 8) * JP + n] = make_float2(acc[mi][ni][2], acc[mi][ni][3]);
        }
    }
}

// ---------------- G2: D[o=128][x=128-tile] = sum_j A*[bases;h] ---------------
// epilogue: + conv_b + f0*mask, gelu, bf16 split write, x0 partials
__global__ __launch_bounds__(256, 2) void k_mma_g2(int cur, int nxt,
                                                   const float* __restrict__ conv_b,
                                                   int l, int dogelu, int dox0) {
    extern __shared__ __align__(128) char dsm[];
    __shared__ float scb[128];
    __shared__ float s_wm[128];
    __shared__ float s_f0[128];
    __shared__ float s_mask[128];
    __shared__ float s_part[128][16];
    const uint32_t sb0 = smem_to_u32(dsm);
    const int tid = threadIdx.x, lane = tid & 31, wid = tid >> 5;
    const int wmi = wid >> 2, wni = wid & 3;
    const int xt = blockIdx.x, b = blockIdx.y;
    if (tid < 128) {
        scb[tid] = conv_b[l * CC + tid];
        s_wm[tid] = g_wm[(size_t)b * NN + (size_t)xt * 128 + tid];
        s_f0[tid] = g_f0[b * CC + tid];
        s_mask[tid] = g_mask[(size_t)b * NN + (size_t)xt * 128 + tid];
    }
    const __nv_bfloat16* Ah = g_Ah + (size_t)b * CC * KA;
    const __nv_bfloat16* Al = g_Al + (size_t)b * CC * KA;
    const __nv_bfloat16* Bbh = g_b16h + (size_t)b * 256 * NN + (size_t)xt * 128;
    const __nv_bfloat16* Bbl = g_b16l + (size_t)b * 256 * NN + (size_t)xt * 128;
    const __nv_bfloat16* Hh = g_h16h[cur] + (size_t)b * CC * NN + (size_t)xt * 128;
    const __nv_bfloat16* Hl = g_h16l[cur] + (size_t)b * CC * NN + (size_t)xt * 128;
    float acc[4][4][4] = {};
    const int niter = KA / 32;   // 12
    fill_g2(sb0, 0, tid, Ah, Al, Bbh, Bbl, Hh, Hl);
    CP_COMMIT;
    fill_g2(sb0 + STG, 32, tid, Ah, Al, Bbh, Bbl, Hh, Hl);
    CP_COMMIT;
    int fs = 2;
    for (int it = 0; it < niter; ++it) {
        CP_WAIT1;
        __syncthreads();
        if (it + 2 < niter) {
            fill_g2(sb0 + (uint32_t)fs * STG, (it + 2) * 32, tid, Ah, Al, Bbh, Bbl, Hh, Hl);
        }
        CP_COMMIT;
        const int cs = (fs + 1 == NSTAGE) ? 0 : fs + 1;
        compute_chunk<true>(sb0 + (uint32_t)((it % NSTAGE)) * STG, wmi, wni, lane, acc);
        fs = cs;
    }
    __syncthreads();
    __nv_bfloat16* hh = g_h16h[nxt] + (size_t)b * CC * NN + (size_t)xt * 128;
    __nv_bfloat16* hl = g_h16l[nxt] + (size_t)b * CC * NN + (size_t)xt * 128;
    float sx[8] = {};
    #pragma unroll
    for (int mi = 0; mi < 4; mi++) {
        #pragma unroll
        for (int ni = 0; ni < 4; ni++) {
            const int n = wni * 32 + ni * 8 + (lane & 3) * 2;
            #pragma unroll
            for (int half = 0; half < 2; half++) {
                const int o = wmi * 64 + mi * 16 + (lane >> 2) + half * 8;
                const float f0o = s_f0[o];
                float v0 = acc[mi][ni][half * 2 + 0] + scb[o] + f0o * s_mask[n];
                float v1 = acc[mi][ni][half * 2 + 1] + scb[o] + f0o * s_mask[n + 1];
                if (dogelu) { v0 = gelu_f(v0); v1 = gelu_f(v1); }
                uint32_t pl, ph = pack_split2(v0, v1, &pl);
                *(uint32_t*)&hh[(size_t)o * NN + n] = ph;
                *(uint32_t*)&hl[(size_t)o * NN + n] = pl;
                if (dox0) {
                    sx[mi * 2 + half] = fmaf(v0, s_wm[n], sx[mi * 2 + half]);
                    sx[mi * 2 + half] = fmaf(v1, s_wm[n + 1], sx[mi * 2 + half]);
                }
            }
        }
    }
    if (dox0) {
        const int slot = wni * 4 + (lane & 3);
        #pragma unroll
        for (int mi = 0; mi < 4; mi++)
            #pragma unroll
            for (int half = 0; half < 2; half++) {
                const int o = wmi * 64 + mi * 16 + (lane >> 2) + half * 8;
                s_part[o][slot] = sx[mi * 2 + half];
            }
        __syncthreads();
        if (tid < 128) {
            float s = 0.f;
            #pragma unroll
            for (int q = 0; q < 16; q++) s += s_part[tid][q];
            g_x0p[xt][b * CC + tid] = s;
        }
    }
}

// ---------------- final MLP as MMA: y[x] = fc2 . gelu(fc1T @ h + b1) + b2 ----
__global__ __launch_bounds__(256, 2) void k_final_mma(const float* __restrict__ fc1_b,
                                                      const float* __restrict__ fc2_w,
                                                      const float* __restrict__ fc2_b,
                                                      float* __restrict__ out) {
    extern __shared__ __align__(128) char dsm[];
    __shared__ float s_fb[128];
    __shared__ float s_w2[128];
    __shared__ float s_red[128][17];
    const uint32_t sb0 = smem_to_u32(dsm);
    const int tid = threadIdx.x, lane = tid & 31, wid = tid >> 5;
    const int wmi = wid >> 2, wni = wid & 3;
    const int xt = blockIdx.x, b = blockIdx.y;
    if (tid < 128) { s_fb[tid] = fc1_b[tid]; s_w2[tid] = fc2_w[tid]; }
    const __nv_bfloat16* Hh = g_h16h[0] + (size_t)b * CC * NN + (size_t)xt * 128;
    const __nv_bfloat16* Hl = g_h16l[0] + (size_t)b * CC * NN + (size_t)xt * 128;
    float acc[4][4][4] = {};
    const int niter = CC / 32;   // 4
    fill_fc(sb0, 0, tid, Hh, Hl);
    CP_COMMIT;
    fill_fc(sb0 + STG, 32, tid, Hh, Hl);
    CP_COMMIT;
    int fs = 2;
    for (int it = 0; it < niter; ++it) {
        CP_WAIT1;
        __syncthreads();
        if (it + 2 < niter) {
            fill_fc(sb0 + (uint32_t)fs * STG, (it + 2) * 32, tid, Hh, Hl);
        }
        CP_COMMIT;
        const int cs = (fs + 1 == NSTAGE) ? 0 : fs + 1;
        compute_chunk<true>(sb0 + (uint32_t)((it % NSTAGE)) * STG, wmi, wni, lane, acc);
        fs = cs;
    }
    __syncthreads();
    float xs[8] = {};
    #pragma unroll
    for (int mi = 0; mi < 4; mi++) {
        #pragma unroll
        for (int ni = 0; ni < 4; ni++) {
            #pragma unroll
            for (int half = 0; half < 2; half++) {
                const int f = wmi * 64 + mi * 16 + (lane >> 2) + half * 8;
                const float w2 = s_w2[f], b1 = s_fb[f];
                xs[ni * 2 + 0] = fmaf(w2, gelu_f(acc[mi][ni][half * 2 + 0] + b1), xs[ni * 2 + 0]);
                xs[ni * 2 + 1] = fmaf(w2, gelu_f(acc[mi][ni][half * 2 + 1] + b1), xs[ni * 2 + 1]);
            }
        }
    }
    const int slot = wmi * 8 + (lane >> 2);
    #pragma unroll
    for (int ni = 0; ni < 4; ni++) {
        #pragma unroll
        for (int p = 0; p < 2; p++) {
            const int x = wni * 32 + ni * 8 + (lane & 3) * 2 + p;
            s_red[x][slot] = xs[ni * 2 + p];
        }
    }
    __syncthreads();
    if (tid < 128) {
        float s = fc2_b[0];
        #pragma unroll
        for (int q = 0; q < 16; q++) s += s_red[tid][q];
        out[(size_t)b * NN + (size_t)xt * 128 + tid] = s;
    }
}

// ---------------- weight transpose (once) ------------------------------------
__global__ void k_wtrans(const float* __restrict__ wc, const float* __restrict__ ws) {
    __shared__ float sm[32][33];
    const int tile = blockIdx.x;
    const int o0 = (tile >> 2) * 32, k0 = (tile & 3) * 32;
    const int i = blockIdx.y, l = blockIdx.z;
    const float scale = 1.0f / 8192.0f;
    for (int w = 0; w < 2; w++) {
        const float* src = w ? ws : wc;
        float* dst = w ? g_wst : g_wct;
        #pragma unroll
        for (int s = 0; s < 4; s++) {
            int oo = threadIdx.y + 8 * s, kk = threadIdx.x;
            sm[oo][kk] = src[(((size_t)l * CC + i) * CC + (o0 + oo)) * KK + (k0 + kk)] * scale;
        }
        __syncthreads();
        #pragma unroll
        for (int s = 0; s < 4; s++) {
            int kk = threadIdx.y + 8 * s, oo = threadIdx.x;
            dst[(((size_t)l * KK + (k0 + kk)) * CC + i) * CC + (o0 + oo)] = sm[oo][kk];
        }
        __syncthreads();
    }
}

// ---------------- fc1^T split prep (once, tiny) -------------------------------
__global__ void k_prepfc(const float* __restrict__ fc1_w) {
    const int f = blockIdx.x, c = threadIdx.x;
    __nv_bfloat16 hi, lo;
    split_bf16(fc1_w[c * CC + f], &hi, &lo);
    g_fc1h[f * CC + c] = hi;
    g_fc1l[f * CC + c] = lo;
}

// ---------------- precompute: bases16, wb16, wm, mask, h0 (2 x/thread) -------
__global__ __launch_bounds__(256) void k_pre(const float* __restrict__ xin,
                                             const float* __restrict__ modes,
                                             const float* __restrict__ fc0_w,
                                             const float* __restrict__ fc0_b) {
    __shared__ float sm_modes[256];
    __shared__ float sm_w[384];
    __shared__ float sm_b[128];
    const int t = threadIdx.x;
    sm_modes[t] = modes[t];
    sm_w[t] = fc0_w[t];
    if (t < 128) { sm_w[256 + t] = fc0_w[256 + t]; sm_b[t] = fc0_b[t]; }
    __syncthreads();

    const int gid = (blockIdx.x * 256 + t) * 2;       // even x pair over B*N
    const int b = gid / NN, xx = gid - b * NN;
    const float* xr = xin + (size_t)gid * 7;
    const float p0i0 = xr[0], p0i1 = xr[1], p0i2 = xr[2];
    const float p0d0 = xr[3], p0d1 = xr[4], p0w = xr[5], p0m = xr[6];
    const float p1i0 = xr[7], p1i1 = xr[8], p1i2 = xr[9];
    const float p1d0 = xr[10], p1d1 = xr[11], p1w = xr[12], p1m = xr[13];

    const float wsz0 = p0w * (float)NN, wsz1 = p1w * (float)NN;
    *(float2*)&g_wm[gid] = make_float2(wsz0 * p0m, wsz1 * p1m);
    *(float2*)&g_mask[gid] = make_float2(p0m, p1m);

    uint32_t* bh = (uint32_t*)(g_b16h + (size_t)b * 256 * NN + xx);
    uint32_t* bl = (uint32_t*)(g_b16l + (size_t)b * 256 * NN + xx);
    uint32_t* wbh = (uint32_t*)(g_wb16h + (size_t)b * 256 * NN + xx);
    uint32_t* wbl = (uint32_t*)(g_wb16l + (size_t)b * 256 * NN + xx);
    #pragma unroll 2
    for (int k = 0; k < KK; k++) {
        const float m0 = sm_modes[2 * k], m1 = sm_modes[2 * k + 1];
        float s0, c0, s1, c1;
        fast_sincos(fmaf(p0d0, m0, p0d1 * m1), &s0, &c0);
        fast_sincos(fmaf(p1d0, m0, p1d1 * m1), &s1, &c1);
        const float cm0 = c0 * p0m, sm0 = s0 * p0m;
        const float cm1 = c1 * p1m, sm1 = s1 * p1m;
        uint32_t lo, hi;
        hi = pack_split2(cm0, cm1, &lo);
        bh[(size_t)k * (NN / 2)] = hi; bl[(size_t)k * (NN / 2)] = lo;
        hi = pack_split2(sm0, sm1, &lo);
        bh[(size_t)(128 + k) * (NN / 2)] = hi; bl[(size_t)(128 + k) * (NN / 2)] = lo;
        hi = pack_split2(cm0 * wsz0, cm1 * wsz1, &lo);
        wbh[(size_t)k * (NN / 2)] = hi; wbl[(size_t)k * (NN / 2)] = lo;
        hi = pack_split2(sm0 * wsz0, sm1 * wsz1, &lo);
        wbh[(size_t)(128 + k) * (NN / 2)] = hi; wbl[(size_t)(128 + k) * (NN / 2)] = lo;
    }
    uint32_t* h16h = (uint32_t*)(g_h16h[0] + (size_t)b * CC * NN + xx);
    uint32_t* h16l = (uint32_t*)(g_h16l[0] + (size_t)b * CC * NN + xx);
    #pragma unroll 4
    for (int c = 0; c < CC; c++) {
        float v0 = sm_b[c], v1 = sm_b[c];
        v0 = fmaf(p0i0, sm_w[c], v0);
        v0 = fmaf(p0i1, sm_w[128 + c], v0);
        v0 = fmaf(p0i2, sm_w[256 + c], v0);
        v1 = fmaf(p1i0, sm_w[c], v1);
        v1 = fmaf(p1i1, sm_w[128 + c], v1);
        v1 = fmaf(p1i2, sm_w[256 + c], v1);
        uint32_t lo, hi = pack_split2(v0, v1, &lo);
        h16h[(size_t)c * (NN / 2)] = hi;
        h16l[(size_t)c * (NN / 2)] = lo;
    }
}

// ---------------- x_0 partials for layer 0 (reads h0 splits) ------------------
__global__ __launch_bounds__(256) void k_x0() {
    const int b = blockIdx.x;
    const int i = blockIdx.y * 8 + (threadIdx.x >> 5);
    const int z = blockIdx.z;
    const int lane = threadIdx.x & 31;
    const int q = NN / 32;
    const uint4* hp = (const uint4*)(g_h16h[0] + ((size_t)b * CC + i) * NN) + (size_t)z * q;
    const uint4* lp = (const uint4*)(g_h16l[0] + ((size_t)b * CC + i) * NN) + (size_t)z * q;
    const float4* wp = (const float4*)(g_wm + (size_t)b * NN) + (size_t)z * q * 2;
    float s = 0.f;
    for (int t = lane; t < q; t += 32) {
        uint4 hv = hp[t], lv = lp[t];
        float4 w0 = wp[2 * t], w1 = wp[2 * t + 1];
        float2 v0 = rec2(hv.x, lv.x), v1 = rec2(hv.y, lv.y);
        float2 v2 = rec2(hv.z, lv.z), v3 = rec2(hv.w, lv.w);
        s = fmaf(v0.x, w0.x, s); s = fmaf(v0.y, w0.y, s);
        s = fmaf(v1.x, w0.z, s); s = fmaf(v1.y, w0.w, s);
        s = fmaf(v2.x, w1.x, s); s = fmaf(v2.y, w1.y, s);
        s = fmaf(v3.x, w1.z, s); s = fmaf(v3.y, w1.w, s);
    }
    #pragma unroll
    for (int off = 16; off; off >>= 1) s += __shfl_xor_sync(0xffffffffu, s, off);
    if (!lane) g_x0p[z][b * CC + i] = s;
}

// ---------------- k_fmix: per-k complex mix -> A rows [2f_c, -2f_s] ----------
__global__ __launch_bounds__(128) void k_fmix(int l) {
    const int t = threadIdx.x;
    const int k = blockIdx.x;
    const int bh = blockIdx.y * 8;
    __shared__ float xc_s[128][8];
    __shared__ float xs_s[128][8];
    #pragma unroll
    for (int b = 0; b < 8; b++) {
        float sc = 0.f, ss = 0.f;
        #pragma unroll
        for (int s = 0; s < NSPLIT; s++) {
            const float* pp = g_part + (((size_t)s * BB + bh + b) * CC + t) * JP;
            sc += pp[k];
            ss += pp[128 + k];
        }
        xc_s[t][b] = sc;
        xs_s[t][b] = -ss;
    }
    __syncthreads();
    float fc[8] = {}, fs[8] = {};
    const float* wcp = g_wct + ((size_t)(l * KK + k)) * CC * CC + t;
    const float* wsp = g_wst + ((size_t)(l * KK + k)) * CC * CC + t;
    #pragma unroll 4
    for (int i = 0; i < 128; i++) {
        const float wcv = wcp[(size_t)i * CC], wsv = wsp[(size_t)i * CC];
        #pragma unroll
        for (int b = 0; b < 8; b++) {
            const float cv = xc_s[i][b], sv = xs_s[i][b];
            fc[b] = fmaf(cv, wcv, fc[b]); fc[b] = fmaf(-sv, wsv, fc[b]);
            fs[b] = fmaf(sv, wcv, fs[b]); fs[b] = fmaf(cv, wsv, fs[b]);
        }
    }
    #pragma unroll
    for (int b = 0; b < 8; b++) {
        const size_t base = ((size_t)(bh + b) * CC + t) * KA;
        __nv_bfloat16 hi, lo;
        split_bf16(2.f * fc[b], &hi, &lo);
        g_Ah[base + k] = hi; g_Al[base + k] = lo;
        split_bf16(-2.f * fs[b], &hi, &lo);
        g_Ah[base + 128 + k] = hi; g_Al[base + 128 + k] = lo;
    }
}

// ---------------- launch -------------------------------------------------------
extern "C" void kernel_launch(void* const* d_in, const int* in_sizes, int n_in,
                              void* d_out, int out_size) {
    const float* x      = (const float*)d_in[0];
    const float* modes  = (const float*)d_in[1];
    const float* fc0_w  = (const float*)d_in[2];
    const float* fc0_b  = (const float*)d_in[3];
    const float* wc     = (const float*)d_in[4];
    const float* ws     = (const float*)d_in[5];
    const float* w0     = (const float*)d_in[6];
    const float* conv_w = (const float*)d_in[7];
    const float* conv_b = (const float*)d_in[8];
    const float* fc1_w  = (const float*)d_in[9];
    const float* fc1_b  = (const float*)d_in[10];
    const float* fc2_w  = (const float*)d_in[11];
    const float* fc2_b  = (const float*)d_in[12];
    float* out = (float*)d_out;

    const int smem = NSTAGE * (int)STG;   // 96KB
    cudaFuncSetAttribute(k_mma_g1, cudaFuncAttributeMaxDynamicSharedMemorySize, smem);
    cudaFuncSetAttribute(k_mma_g2, cudaFuncAttributeMaxDynamicSharedMemorySize, smem);
    cudaFuncSetAttribute(k_final_mma, cudaFuncAttributeMaxDynamicSharedMemorySize, smem);

    k_wtrans<<<dim3(16, 128, 4), dim3(32, 8)>>>(wc, ws);
    k_prepfc<<<CC, CC>>>(fc1_w);
    k_pre<<<(BB * NN) / 512, 256>>>(x, modes, fc0_w, fc0_b);
    k_x0<<<dim3(BB, 16, 4), 256>>>();
    for (int l = 0; l < LL; l++) {
        const int cur = l & 1, nxt = cur ^ 1;
        k_mma_g1<<<dim3(2, NSPLIT, BB + 1), 256, smem>>>(cur, w0, conv_w, l,
                                                         (l == 0) ? 4 : 64);
        k_fmix<<<dim3(128, 2), 128>>>(l);
        k_mma_g2<<<dim3(NN / 128, BB), 256, smem>>>(cur, nxt, conv_b, l,
                                                    (l < LL - 1) ? 1 : 0,
                                                    (l < LL - 1) ? 1 : 0);
    }
    k_final_mma<<<dim3(NN / 128, BB), 256, smem>>>(fc1_b, fc2_w, fc2_b, out);
}